// round 3
// baseline (speedup 1.0000x reference)
#include <cuda_runtime.h>

#define Bq  2
#define Sq  2048
#define Dq  1024
#define Hq  16
#define DKV 64

// ---------------- scratch (static device arrays; no cudaMalloc) -------------
__device__ float g_Q[Bq * Hq * Sq * DKV];      // [b,h,s,dkv]
__device__ float g_K[Bq * Hq * Sq * DKV];
__device__ float g_V[Bq * Hq * Sq * DKV];
__device__ float g_ctx[Bq * Sq * Dq];          // [b,s,d]
__device__ float g_rowsum[Bq * Hq * Sq];
__device__ float g_bias[Hq * 4096];            // [h][delta], delta = k-q+2048

// ---------------- fast exp in the FMA pipe ----------------------------------
__device__ __forceinline__ float fexp(float x) {
    float t = x * 1.4426950408889634f;
    t = fmaxf(t, -126.0f);
    float nf = floorf(t);
    float u = (t - nf) * 0.6931471805599453f;    // [0, ln2)
    float p = fmaf(u, 1.0f / 720.0f, 1.0f / 120.0f);
    p = fmaf(p, u, 1.0f / 24.0f);
    p = fmaf(p, u, 1.0f / 6.0f);
    p = fmaf(p, u, 0.5f);
    p = fmaf(p, u, 1.0f);
    p = fmaf(p, u, 1.0f);
    int ei = (int)nf;
    return p * __int_as_float((ei + 127) << 23);
}

// ---------------- T5 relative-position bias table ---------------------------
__global__ void bias_init(const float* __restrict__ rel_bias) {
    int d = blockIdx.x * 256 + threadIdx.x;
    if (d >= 4096) return;
    int n = -(d - 2048);
    int ret = 0;
    if (n < 0) { ret = 16; n = -n; }
    int bucket;
    if      (n <  8) bucket = n;
    else if (n < 12) bucket = 8;
    else if (n < 16) bucket = 9;
    else if (n < 23) bucket = 10;
    else if (n < 32) bucket = 11;
    else if (n < 46) bucket = 12;
    else if (n < 64) bucket = 13;
    else if (n < 91) bucket = 14;
    else             bucket = 15;
    bucket += ret;
    #pragma unroll
    for (int h = 0; h < Hq; h++)
        g_bias[h * 4096 + d] = rel_bias[bucket * Hq + h];
}

// ---------------- 4096x1024 @ 1024x1024 GEMM: 128x128 tile, 8x8 micro -------
__global__ __launch_bounds__(256, 2) void gemm4096(
    const float* __restrict__ Xin, const float* __restrict__ W,
    float* __restrict__ Yrm, int mode)
{
    __shared__ float Xs[16][132];   // [k][m] transposed
    __shared__ float Ws[16][132];   // [k][n]
    const float* X = (mode == 3) ? g_ctx : Xin;
    const int m0 = blockIdx.y << 7;
    const int n0 = blockIdx.x << 7;
    const int t = threadIdx.x;
    const int tx = t & 15, ty = t >> 4;
    const int xr = t >> 2, xc = (t & 3) << 2;   // X: 64 rows x 16 cols per pass
    const int wr = t >> 4, wc = (t & 15) << 2;  // W: 16 rows x 64 cols per pass

    float4 xv0 = *(const float4*)&X[(m0 + xr) * Dq + xc];
    float4 xv1 = *(const float4*)&X[(m0 + 64 + xr) * Dq + xc];
    float4 wv0 = *(const float4*)&W[wr * Dq + n0 + wc];
    float4 wv1 = *(const float4*)&W[wr * Dq + n0 + 64 + wc];

    float acc[8][8] = {};
    for (int k0 = 0; k0 < Dq; k0 += 16) {
        __syncthreads();
        Xs[xc + 0][xr] = xv0.x; Xs[xc + 1][xr] = xv0.y;
        Xs[xc + 2][xr] = xv0.z; Xs[xc + 3][xr] = xv0.w;
        Xs[xc + 0][64 + xr] = xv1.x; Xs[xc + 1][64 + xr] = xv1.y;
        Xs[xc + 2][64 + xr] = xv1.z; Xs[xc + 3][64 + xr] = xv1.w;
        *(float4*)&Ws[wr][wc] = wv0;
        *(float4*)&Ws[wr][64 + wc] = wv1;
        __syncthreads();
        if (k0 + 16 < Dq) {                      // prefetch next slab
            xv0 = *(const float4*)&X[(m0 + xr) * Dq + k0 + 16 + xc];
            xv1 = *(const float4*)&X[(m0 + 64 + xr) * Dq + k0 + 16 + xc];
            wv0 = *(const float4*)&W[(k0 + 16 + wr) * Dq + n0 + wc];
            wv1 = *(const float4*)&W[(k0 + 16 + wr) * Dq + n0 + 64 + wc];
        }
        #pragma unroll
        for (int kk = 0; kk < 16; kk++) {
            float4 a0 = *(const float4*)&Xs[kk][ty << 2];
            float4 a1 = *(const float4*)&Xs[kk][64 + (ty << 2)];
            float4 b0 = *(const float4*)&Ws[kk][tx << 2];
            float4 b1 = *(const float4*)&Ws[kk][64 + (tx << 2)];
            float a[8] = {a0.x, a0.y, a0.z, a0.w, a1.x, a1.y, a1.z, a1.w};
            float bb[8] = {b0.x, b0.y, b0.z, b0.w, b1.x, b1.y, b1.z, b1.w};
            #pragma unroll
            for (int r = 0; r < 8; r++)
                #pragma unroll
                for (int c = 0; c < 8; c++)
                    acc[r][c] = fmaf(a[r], bb[c], acc[r][c]);
        }
    }

    if (mode <= 2) {
        float* dst = (mode == 0) ? g_Q : (mode == 1) ? g_K : g_V;
        const int h0 = n0 >> 6;                  // group0 head, group1 = h0+1
        const int dv = tx << 2;
        #pragma unroll
        for (int r = 0; r < 8; r++) {
            int m = m0 + ((r < 4) ? (ty << 2) + r : 64 + (ty << 2) + r - 4);
            int b = m >> 11, s = m & 2047;
            *(float4*)&dst[((b * Hq + h0) * Sq + s) * DKV + dv] =
                make_float4(acc[r][0], acc[r][1], acc[r][2], acc[r][3]);
            *(float4*)&dst[((b * Hq + h0 + 1) * Sq + s) * DKV + dv] =
                make_float4(acc[r][4], acc[r][5], acc[r][6], acc[r][7]);
        }
    } else {
        #pragma unroll
        for (int r = 0; r < 8; r++) {
            int m = m0 + ((r < 4) ? (ty << 2) + r : 64 + (ty << 2) + r - 4);
            *(float4*)&Yrm[m * Dq + n0 + (tx << 2)] =
                make_float4(acc[r][0], acc[r][1], acc[r][2], acc[r][3]);
            *(float4*)&Yrm[m * Dq + n0 + 64 + (tx << 2)] =
                make_float4(acc[r][4], acc[r][5], acc[r][6], acc[r][7]);
        }
    }
}

// ---------------- scores: store exp(QK/8 + bias) (masked->0) + row sums -----
__global__ __launch_bounds__(256, 2) void attn_scores(
    const int* __restrict__ mask, float* __restrict__ attn)
{
    __shared__ float Qs[64][132];   // [dkv][q]
    __shared__ float Ks[64][132];   // [dkv][k]
    __shared__ float biasW[256];
    __shared__ int   maskS[128];
    const int q0 = blockIdx.x << 7;
    const int h = blockIdx.y, b = blockIdx.z;
    const int bh = b * Hq + h;
    const int t = threadIdx.x;
    const int tx = t & 15, ty = t >> 4;

    #pragma unroll
    for (int p = 0; p < 8; p++) {                // Q tile once, transposed
        int idx = t + (p << 8);
        int row = idx >> 4, c4 = (idx & 15) << 2;
        float4 v = *(const float4*)&g_Q[(bh * Sq + q0 + row) * DKV + c4];
        Qs[c4 + 0][row] = v.x; Qs[c4 + 1][row] = v.y;
        Qs[c4 + 2][row] = v.z; Qs[c4 + 3][row] = v.w;
    }
    float rsum[8] = {};
    for (int k0 = 0; k0 < Sq; k0 += 128) {
        __syncthreads();
        #pragma unroll
        for (int p = 0; p < 8; p++) {            // K tile, transposed
            int idx = t + (p << 8);
            int row = idx >> 4, c4 = (idx & 15) << 2;
            float4 v = *(const float4*)&g_K[(bh * Sq + k0 + row) * DKV + c4];
            Ks[c4 + 0][row] = v.x; Ks[c4 + 1][row] = v.y;
            Ks[c4 + 2][row] = v.z; Ks[c4 + 3][row] = v.w;
        }
        if (t < 255) biasW[t] = g_bias[h * 4096 + (k0 - q0 + t - 127 + 2048)];
        if (t < 128) maskS[t] = mask[b * Sq + k0 + t];
        __syncthreads();

        float acc[8][8] = {};
        #pragma unroll 8
        for (int kk = 0; kk < 64; kk++) {
            float4 a0 = *(const float4*)&Qs[kk][ty << 2];
            float4 a1 = *(const float4*)&Qs[kk][64 + (ty << 2)];
            float4 b0 = *(const float4*)&Ks[kk][tx << 2];
            float4 b1 = *(const float4*)&Ks[kk][64 + (tx << 2)];
            float a[8] = {a0.x, a0.y, a0.z, a0.w, a1.x, a1.y, a1.z, a1.w};
            float bb[8] = {b0.x, b0.y, b0.z, b0.w, b1.x, b1.y, b1.z, b1.w};
            #pragma unroll
            for (int r = 0; r < 8; r++)
                #pragma unroll
                for (int c = 0; c < 8; c++)
                    acc[r][c] = fmaf(a[r], bb[c], acc[r][c]);
        }
        #pragma unroll
        for (int r = 0; r < 8; r++) {
            int qr = (r < 4) ? (ty << 2) + r : 64 + (ty << 2) + r - 4;
            #pragma unroll
            for (int g = 0; g < 2; g++) {
                int kc0 = (g << 6) + (tx << 2);
                float4 e;
                float* ep = &e.x;
                #pragma unroll
                for (int c = 0; c < 4; c++) {
                    int kc = kc0 + c;
                    float sc = fmaf(acc[r][(g << 2) + c], 0.125f, biasW[kc - qr + 127]);
                    float ee = (maskS[kc] == 0) ? 0.0f : fexp(sc);
                    ep[c] = ee;
                    rsum[r] += ee;
                }
                *(float4*)&attn[(size_t)(bh * Sq + q0 + qr) * Sq + k0 + kc0] = e;
            }
        }
    }
    #pragma unroll
    for (int r = 0; r < 8; r++) {
        float e = rsum[r];
        e += __shfl_xor_sync(0xffffffffu, e, 8, 16);
        e += __shfl_xor_sync(0xffffffffu, e, 4, 16);
        e += __shfl_xor_sync(0xffffffffu, e, 2, 16);
        e += __shfl_xor_sync(0xffffffffu, e, 1, 16);
        if (tx == 0) {
            int qr = (r < 4) ? (ty << 2) + r : 64 + (ty << 2) + r - 4;
            g_rowsum[bh * Sq + q0 + qr] = e;
        }
    }
}

// ---------------- context: P = e/l written in place; ctx = P @ V ------------
__global__ __launch_bounds__(128) void attn_ctx(float* __restrict__ attn)
{
    __shared__ float Ps[64][132];   // [k][q]
    __shared__ float Vs[64][68];    // [k][dv]
    __shared__ float rinv[128];
    const int q0 = blockIdx.x << 7;
    const int h = blockIdx.y, b = blockIdx.z;
    const int bh = b * Hq + h;
    const int t = threadIdx.x;
    const int tx = t & 7, ty = t >> 3;
    rinv[t] = 1.0f / g_rowsum[bh * Sq + q0 + t];

    float acc[8][8] = {};
    for (int k0 = 0; k0 < Sq; k0 += 64) {
        __syncthreads();
        #pragma unroll
        for (int p = 0; p < 16; p++) {           // P tile: normalize + writeback
            int idx = t + (p << 7);
            int row = idx >> 4, c4 = (idx & 15) << 2;
            size_t gi = (size_t)(bh * Sq + q0 + row) * Sq + k0 + c4;
            float4 v = *(const float4*)&attn[gi];
            float ri = rinv[row];
            v.x *= ri; v.y *= ri; v.z *= ri; v.w *= ri;
            *(float4*)&attn[gi] = v;             // final attn_weights output
            Ps[c4 + 0][row] = v.x; Ps[c4 + 1][row] = v.y;
            Ps[c4 + 2][row] = v.z; Ps[c4 + 3][row] = v.w;
        }
        #pragma unroll
        for (int p = 0; p < 8; p++) {            // V tile
            int idx = t + (p << 7);
            int row = idx >> 4, c4 = (idx & 15) << 2;
            *(float4*)&Vs[row][c4] =
                *(const float4*)&g_V[(bh * Sq + k0 + row) * DKV + c4];
        }
        __syncthreads();
        #pragma unroll 8
        for (int kk = 0; kk < 64; kk++) {
            float4 a0 = *(const float4*)&Ps[kk][ty << 2];
            float4 a1 = *(const float4*)&Ps[kk][64 + (ty << 2)];
            float4 b0 = *(const float4*)&Vs[kk][tx << 2];
            float4 b1 = *(const float4*)&Vs[kk][32 + (tx << 2)];
            float a[8] = {a0.x, a0.y, a0.z, a0.w, a1.x, a1.y, a1.z, a1.w};
            float bb[8] = {b0.x, b0.y, b0.z, b0.w, b1.x, b1.y, b1.z, b1.w};
            #pragma unroll
            for (int r = 0; r < 8; r++)
                #pragma unroll
                for (int c = 0; c < 8; c++)
                    acc[r][c] = fmaf(a[r], bb[c], acc[r][c]);
        }
    }
    #pragma unroll
    for (int r = 0; r < 8; r++) {
        int q = q0 + ((r < 4) ? (ty << 2) + r : 64 + (ty << 2) + r - 4);
        *(float4*)&g_ctx[(b * Sq + q) * Dq + (h << 6) + (tx << 2)] =
            make_float4(acc[r][0], acc[r][1], acc[r][2], acc[r][3]);
        *(float4*)&g_ctx[(b * Sq + q) * Dq + (h << 6) + 32 + (tx << 2)] =
            make_float4(acc[r][4], acc[r][5], acc[r][6], acc[r][7]);
    }
}

// ---------------- launch -----------------------------------------------------
extern "C" void kernel_launch(void* const* d_in, const int* in_sizes, int n_in,
                              void* d_out, int out_size)
{
    const float* hs   = (const float*)d_in[0];
    const int*   mask = (const int*)d_in[1];
    const float* Wq   = (const float*)d_in[2];
    const float* Wk   = (const float*)d_in[3];
    const float* Wv   = (const float*)d_in[4];
    const float* Wo   = (const float*)d_in[5];
    const float* rb   = (const float*)d_in[6];
    float* out  = (float*)d_out;                           // [2,2048,1024]
    float* attn = out + (size_t)Bq * Sq * Dq;              // [2,16,2048,2048]

    bias_init<<<16, 256>>>(rb);

    dim3 gp(Dq / 128, (Bq * Sq) / 128);          // (8, 32)
    gemm4096<<<gp, 256>>>(hs, Wq, nullptr, 0);
    gemm4096<<<gp, 256>>>(hs, Wk, nullptr, 1);
    gemm4096<<<gp, 256>>>(hs, Wv, nullptr, 2);

    dim3 ga(Sq / 128, Hq, Bq);                   // (16, 16, 2)
    attn_scores<<<ga, 256>>>(mask, attn);
    attn_ctx<<<ga, 128>>>(attn);

    gemm4096<<<gp, 256>>>(nullptr, Wo, out, 3);
}

// round 5
// speedup vs baseline: 1.8006x; 1.8006x over previous
#include <cuda_runtime.h>
#include <cuda_bf16.h>
#include <cstdint>

// ---------------- scratch (static device arrays; no cudaMalloc) -------------
__device__ __align__(16) __nv_bfloat16 g_Xhi[4194304], g_Xlo[4194304];
__device__ __align__(16) __nv_bfloat16 g_Whi[4][1048576], g_Wlo[4][1048576];
__device__ __align__(16) __nv_bfloat16 g_Qhi[4194304], g_Qlo[4194304];
__device__ __align__(16) __nv_bfloat16 g_Khi[4194304], g_Klo[4194304];
__device__ __align__(16) __nv_bfloat16 g_Vhi[4194304], g_Vlo[4194304]; // [bh][s][dkv]
__device__ __align__(16) __nv_bfloat16 g_Chi[4194304], g_Clo[4194304]; // [m][1024]
__device__ float g_rowsum[65536];
__device__ float g_bias[16 * 4096];

// ---------------- helpers -----------------------------------------------------
__device__ __forceinline__ uint32_t smem_u32(const void* p) {
    uint32_t a;
    asm("{ .reg .u64 t; cvta.to.shared.u64 t, %1; cvt.u32.u64 %0, t; }" : "=r"(a) : "l"(p));
    return a;
}
__device__ __forceinline__ uint32_t swz(uint32_t off) { return off ^ ((off >> 3) & 0x70); }

__device__ __forceinline__ void ldsm4(uint32_t* r, uint32_t addr) {
    asm volatile("ldmatrix.sync.aligned.m8n8.x4.shared.b16 {%0,%1,%2,%3}, [%4];"
        : "=r"(r[0]), "=r"(r[1]), "=r"(r[2]), "=r"(r[3]) : "r"(addr));
}
__device__ __forceinline__ void ldsm4t(uint32_t* r, uint32_t addr) {
    asm volatile("ldmatrix.sync.aligned.m8n8.x4.trans.shared.b16 {%0,%1,%2,%3}, [%4];"
        : "=r"(r[0]), "=r"(r[1]), "=r"(r[2]), "=r"(r[3]) : "r"(addr));
}
__device__ __forceinline__ void mma16816(float* d, const uint32_t* a, const uint32_t* b) {
    asm volatile("mma.sync.aligned.m16n8k16.row.col.f32.bf16.bf16.f32 "
        "{%0,%1,%2,%3}, {%4,%5,%6,%7}, {%8,%9}, {%0,%1,%2,%3};"
        : "+f"(d[0]), "+f"(d[1]), "+f"(d[2]), "+f"(d[3])
        : "r"(a[0]), "r"(a[1]), "r"(a[2]), "r"(a[3]), "r"(b[0]), "r"(b[1]));
}
// pack 2 fp32 -> bf16x2 hi word + lo (residual) word
__device__ __forceinline__ uint32_t pk2(float a, float b, uint32_t& lo) {
    __nv_bfloat162 h, l;
    h.x = __float2bfloat16_rn(a); h.y = __float2bfloat16_rn(b);
    l.x = __float2bfloat16_rn(a - __bfloat162float(h.x));
    l.y = __float2bfloat16_rn(b - __bfloat162float(h.y));
    lo = *(uint32_t*)&l;
    return *(uint32_t*)&h;
}

// ---------------- prep kernels -------------------------------------------------
__global__ void bias_init(const float* __restrict__ rel_bias) {
    int d = blockIdx.x * 256 + threadIdx.x;
    if (d >= 4096) return;
    int n = -(d - 2048);
    int ret = 0;
    if (n < 0) { ret = 16; n = -n; }
    int bucket;
    if      (n <  8) bucket = n;
    else if (n < 12) bucket = 8;
    else if (n < 16) bucket = 9;
    else if (n < 23) bucket = 10;
    else if (n < 32) bucket = 11;
    else if (n < 46) bucket = 12;
    else if (n < 64) bucket = 13;
    else if (n < 91) bucket = 14;
    else             bucket = 15;
    bucket += ret;
    #pragma unroll
    for (int h = 0; h < 16; h++)
        g_bias[h * 4096 + d] = rel_bias[bucket * 16 + h];
}

__global__ void split_x(const float* __restrict__ src) {
    size_t i = ((size_t)blockIdx.x * 256 + threadIdx.x) * 4;
    float4 v = *(const float4*)(src + i);
    float x[4] = {v.x, v.y, v.z, v.w};
    #pragma unroll
    for (int j = 0; j < 4; j++) {
        __nv_bfloat16 hh = __float2bfloat16_rn(x[j]);
        g_Xhi[i + j] = hh;
        g_Xlo[i + j] = __float2bfloat16_rn(x[j] - __bfloat162float(hh));
    }
}

__global__ void wsplit(const float* __restrict__ W0, const float* __restrict__ W1,
                       const float* __restrict__ W2, const float* __restrict__ W3) {
    __shared__ float tile[32][33];
    const float* W = blockIdx.z == 0 ? W0 : blockIdx.z == 1 ? W1 : blockIdx.z == 2 ? W2 : W3;
    int n0 = blockIdx.x * 32, k0 = blockIdx.y * 32;
    int tx = threadIdx.x, ty = threadIdx.y;
    #pragma unroll
    for (int j = 0; j < 4; j++)
        tile[ty + j * 8][tx] = W[(size_t)(k0 + ty + j * 8) * 1024 + n0 + tx];
    __syncthreads();
    #pragma unroll
    for (int j = 0; j < 4; j++) {
        float x = tile[tx][ty + j * 8];
        __nv_bfloat16 hh = __float2bfloat16_rn(x);
        size_t o = (size_t)(n0 + ty + j * 8) * 1024 + k0 + tx;     // [n][k]
        g_Whi[blockIdx.z][o] = hh;
        g_Wlo[blockIdx.z][o] = __float2bfloat16_rn(x - __bfloat162float(hh));
    }
}

// ---------------- unified 128x128 HMMA GEMM (proj 0/1/2, out 3) ----------------
// A[m][k] (X or ctx), B[n][k] (Wt). 3-term bf16 split. K=1024, chunk=64.
__global__ __launch_bounds__(256) void proj_gemm(float* __restrict__ outp, int mode) {
    extern __shared__ __align__(1024) char smx[];
    const uint32_t sb = smem_u32(smx);
    const int t = threadIdx.x, lane = t & 31, wid = t >> 5;
    const int wm = wid >> 2, wn = wid & 3;
    const int m0 = blockIdx.y << 7, n0 = blockIdx.x << 7;
    const __nv_bfloat16* Ah = (mode == 3) ? g_Chi : g_Xhi;
    const __nv_bfloat16* Al = (mode == 3) ? g_Clo : g_Xlo;
    const __nv_bfloat16* Bh = g_Whi[mode];
    const __nv_bfloat16* Bl = g_Wlo[mode];

    float acc[4][4][4] = {};
    const uint32_t a_row = (lane & 7) + ((lane >> 3) & 1) * 8;
    const uint32_t a_kb  = (lane >> 4) * 16;
    const uint32_t b_row = (lane & 7) + (lane >> 4) * 8;
    const uint32_t b_kb  = ((lane >> 3) & 1) * 16;

    for (int kc = 0; kc < 16; kc++) {
        const int kb = kc << 6;
        __syncthreads();
        #pragma unroll
        for (int i = 0; i < 4; i++) {
            int idx = t + (i << 8);
            int row = idx >> 3, ge = (idx & 7) << 3;
            uint32_t so = swz(row * 128 + (ge << 1));
            size_t goa = (size_t)(m0 + row) * 1024 + kb + ge;
            size_t gob = (size_t)(n0 + row) * 1024 + kb + ge;
            *(uint4*)(smx + so)          = *(const uint4*)(Ah + goa);
            *(uint4*)(smx + 16384 + so)  = *(const uint4*)(Al + goa);
            *(uint4*)(smx + 32768 + so)  = *(const uint4*)(Bh + gob);
            *(uint4*)(smx + 49152 + so)  = *(const uint4*)(Bl + gob);
        }
        __syncthreads();
        #pragma unroll
        for (int ki = 0; ki < 4; ki++) {
            uint32_t ahf[4][4], alf[4][4], bhf[2][4], blf[2][4];
            #pragma unroll
            for (int mi = 0; mi < 4; mi++) {
                uint32_t off = swz(((wm << 6) + (mi << 4) + a_row) * 128 + (ki << 5) + a_kb);
                ldsm4(ahf[mi], sb + off);
                ldsm4(alf[mi], sb + 16384 + off);
            }
            #pragma unroll
            for (int nh = 0; nh < 2; nh++) {
                uint32_t off = swz(((wn << 5) + (nh << 4) + b_row) * 128 + (ki << 5) + b_kb);
                ldsm4(bhf[nh], sb + 32768 + off);
                ldsm4(blf[nh], sb + 49152 + off);
            }
            #pragma unroll
            for (int mi = 0; mi < 4; mi++)
                #pragma unroll
                for (int ni = 0; ni < 4; ni++) {
                    const uint32_t* bh2 = &bhf[ni >> 1][(ni & 1) << 1];
                    const uint32_t* bl2 = &blf[ni >> 1][(ni & 1) << 1];
                    mma16816(acc[mi][ni], ahf[mi], bh2);
                    mma16816(acc[mi][ni], alf[mi], bh2);
                    mma16816(acc[mi][ni], ahf[mi], bl2);
                }
        }
    }

    const int g = lane >> 2, tq = lane & 3;
    #pragma unroll
    for (int mi = 0; mi < 4; mi++) {
        #pragma unroll
        for (int ni = 0; ni < 4; ni++) {
            #pragma unroll
            for (int half = 0; half < 2; half++) {
                int r = (wm << 6) + (mi << 4) + g + half * 8;
                int c = (wn << 5) + (ni << 3) + (tq << 1);
                float v0 = acc[mi][ni][half * 2], v1 = acc[mi][ni][half * 2 + 1];
                int m = m0 + r, n = n0 + c;
                if (mode == 3) {
                    *(float2*)&outp[(size_t)m * 1024 + n] = make_float2(v0, v1);
                } else {
                    uint32_t lo, hi = pk2(v0, v1, lo);
                    int b = m >> 11, s = m & 2047, hd = n >> 6, dk = n & 63;
                    size_t o = (((size_t)(b * 16 + hd) * 2048) + s) * 64 + dk;
                    __nv_bfloat16* dh = (mode == 0) ? g_Qhi : (mode == 1) ? g_Khi : g_Vhi;
                    __nv_bfloat16* dl = (mode == 0) ? g_Qlo : (mode == 1) ? g_Klo : g_Vlo;
                    *(uint32_t*)(dh + o) = hi;
                    *(uint32_t*)(dl + o) = lo;
                }
            }
        }
    }
}

// ---------------- scores: attn = exp(QK/8 + bias), masked->0, rowsums ----------
__global__ __launch_bounds__(256) void attn_scores(const int* __restrict__ mask,
                                                   float* __restrict__ attn) {
    extern __shared__ __align__(1024) char smx[];
    const uint32_t sb = smem_u32(smx);
    float* biasW = (float*)(smx + 65536);
    int*   maskS = (int*)(smx + 66560);
    float* rowsm = (float*)(smx + 67072);
    const int t = threadIdx.x, lane = t & 31, wid = t >> 5;
    const int wm = wid >> 2, wn = wid & 3;
    const int q0 = blockIdx.x << 7, bh = blockIdx.y, b = bh >> 4, h = bh & 15;
    const int g = lane >> 2, tq = lane & 3;

    // Q tiles (hi at 0, lo at 16384), persistent
    #pragma unroll
    for (int i = 0; i < 4; i++) {
        int idx = t + (i << 8);
        int row = idx >> 3, ge = (idx & 7) << 3;
        uint32_t so = swz(row * 128 + (ge << 1));
        size_t go = ((size_t)bh * 2048 + q0 + row) * 64 + ge;
        *(uint4*)(smx + so)         = *(const uint4*)(g_Qhi + go);
        *(uint4*)(smx + 16384 + so) = *(const uint4*)(g_Qlo + go);
    }
    if (t < 128) rowsm[t] = 0.f;

    const uint32_t a_row = (lane & 7) + ((lane >> 3) & 1) * 8;
    const uint32_t a_kb  = (lane >> 4) * 16;
    const uint32_t b_row = (lane & 7) + (lane >> 4) * 8;
    const uint32_t b_kb  = ((lane >> 3) & 1) * 16;

    float rowpart[4][2] = {};
    for (int kt = 0; kt < 16; kt++) {
        const int k0 = kt << 7;
        __syncthreads();
        #pragma unroll
        for (int i = 0; i < 4; i++) {
            int idx = t + (i << 8);
            int row = idx >> 3, ge = (idx & 7) << 3;
            uint32_t so = swz(row * 128 + (ge << 1));
            size_t go = ((size_t)bh * 2048 + k0 + row) * 64 + ge;
            *(uint4*)(smx + 32768 + so) = *(const uint4*)(g_Khi + go);
            *(uint4*)(smx + 49152 + so) = *(const uint4*)(g_Klo + go);
        }
        const int base = k0 - q0 + 1921;
        if (t < 255) biasW[t] = g_bias[h * 4096 + base + t];
        if (t < 128) maskS[t] = mask[b * 2048 + k0 + t];
        __syncthreads();

        float acc[4][4][4] = {};
        #pragma unroll
        for (int ki = 0; ki < 4; ki++) {
            uint32_t ahf[4][4], alf[4][4], bhf[2][4], blf[2][4];
            #pragma unroll
            for (int mi = 0; mi < 4; mi++) {
                uint32_t off = swz(((wm << 6) + (mi << 4) + a_row) * 128 + (ki << 5) + a_kb);
                ldsm4(ahf[mi], sb + off);
                ldsm4(alf[mi], sb + 16384 + off);
            }
            #pragma unroll
            for (int nh = 0; nh < 2; nh++) {
                uint32_t off = swz(((wn << 5) + (nh << 4) + b_row) * 128 + (ki << 5) + b_kb);
                ldsm4(bhf[nh], sb + 32768 + off);
                ldsm4(blf[nh], sb + 49152 + off);
            }
            #pragma unroll
            for (int mi = 0; mi < 4; mi++)
                #pragma unroll
                for (int ni = 0; ni < 4; ni++) {
                    const uint32_t* bh2 = &bhf[ni >> 1][(ni & 1) << 1];
                    const uint32_t* bl2 = &blf[ni >> 1][(ni & 1) << 1];
                    mma16816(acc[mi][ni], ahf[mi], bh2);
                    mma16816(acc[mi][ni], alf[mi], bh2);
                    mma16816(acc[mi][ni], ahf[mi], bl2);
                }
        }
        // epilogue: bias + mask + exp, store, rowsum partials
        #pragma unroll
        for (int mi = 0; mi < 4; mi++) {
            #pragma unroll
            for (int half = 0; half < 2; half++) {
                int r = (wm << 6) + (mi << 4) + g + half * 8;
                float rp = 0.f;
                #pragma unroll
                for (int ni = 0; ni < 4; ni++) {
                    int c = (wn << 5) + (ni << 3) + (tq << 1);
                    float s0 = fmaf(acc[mi][ni][half * 2],     0.125f, biasW[c - r + 127]);
                    float s1 = fmaf(acc[mi][ni][half * 2 + 1], 0.125f, biasW[c + 1 - r + 127]);
                    float e0 = maskS[c]     ? __expf(s0) : 0.f;
                    float e1 = maskS[c + 1] ? __expf(s1) : 0.f;
                    rp += e0 + e1;
                    *(float2*)&attn[((size_t)bh * 2048 + q0 + r) * 2048 + k0 + c] =
                        make_float2(e0, e1);
                }
                rowpart[mi][half] += rp;
            }
        }
    }
    __syncthreads();
    #pragma unroll
    for (int mi = 0; mi < 4; mi++)
        #pragma unroll
        for (int half = 0; half < 2; half++) {
            float v = rowpart[mi][half];
            v += __shfl_xor_sync(0xffffffffu, v, 1);
            v += __shfl_xor_sync(0xffffffffu, v, 2);
            if (tq == 0)
                atomicAdd(&rowsm[(wm << 6) + (mi << 4) + g + half * 8], v);
        }
    __syncthreads();
    if (t < 128) g_rowsum[bh * 2048 + q0 + t] = rowsm[t];
}

// ---------------- ctx: normalize attn in place (final weights), ctx = P @ V ----
__global__ __launch_bounds__(256) void attn_ctx(float* __restrict__ attn) {
    extern __shared__ __align__(1024) char smx[];
    const uint32_t sb = smem_u32(smx);
    float* rinv = (float*)(smx + 49152);
    const int t = threadIdx.x, lane = t & 31, wid = t >> 5;
    const int wm = wid >> 2, wn = wid & 3;
    const int q0 = blockIdx.x << 7, bh = blockIdx.y, b = bh >> 4, h = bh & 15;
    const int g = lane >> 2, tq = lane & 3;
    if (t < 128) rinv[t] = 1.0f / g_rowsum[bh * 2048 + q0 + t];
    __syncthreads();

    const uint32_t a_row = (lane & 7) + ((lane >> 3) & 1) * 8;
    const uint32_t a_kb  = (lane >> 4) * 16;
    const uint32_t v_row = (lane & 7) + ((lane >> 3) & 1) * 8;   // k rows
    const uint32_t v_cb  = (lane >> 4) * 16;                     // n col bytes

    float acc[4][2][4] = {};
    for (int kc = 0; kc < 32; kc++) {
        const int k0 = kc << 6;
        __syncthreads();
        // normalize + writeback + split P into SPh/SPl
        #pragma unroll
        for (int i = 0; i < 8; i++) {
            int idx = t + (i << 8);
            int row = idx >> 4, c4 = (idx & 15) << 2;
            size_t ga = ((size_t)bh * 2048 + q0 + row) * 2048 + k0 + c4;
            float4 v = *(const float4*)&attn[ga];
            float ri = rinv[row];
            v.x *= ri; v.y *= ri; v.z *= ri; v.w *= ri;
            *(float4*)&attn[ga] = v;                       // final attn_weights
            uint32_t l0, h0 = pk2(v.x, v.y, l0);
            uint32_t l1, h1 = pk2(v.z, v.w, l1);
            uint32_t so = swz(row * 128 + (c4 << 1));
            *(uint2*)(smx + so)         = make_uint2(h0, h1);
            *(uint2*)(smx + 16384 + so) = make_uint2(l0, l1);
        }
        // V tiles [k=64 rows][dv=64] hi/lo
        #pragma unroll
        for (int i = 0; i < 2; i++) {
            int idx = t + (i << 8);
            int row = idx >> 3, ge = (idx & 7) << 3;
            uint32_t so = swz(row * 128 + (ge << 1));
            size_t go = ((size_t)bh * 2048 + k0 + row) * 64 + ge;
            *(uint4*)(smx + 32768 + so) = *(const uint4*)(g_Vhi + go);
            *(uint4*)(smx + 40960 + so) = *(const uint4*)(g_Vlo + go);
        }
        __syncthreads();
        #pragma unroll
        for (int ki = 0; ki < 4; ki++) {
            uint32_t ahf[4][4], alf[4][4], bhf[4], blf[4];
            #pragma unroll
            for (int mi = 0; mi < 4; mi++) {
                uint32_t off = swz(((wm << 6) + (mi << 4) + a_row) * 128 + (ki << 5) + a_kb);
                ldsm4(ahf[mi], sb + off);
                ldsm4(alf[mi], sb + 16384 + off);
            }
            {
                uint32_t off = swz(((ki << 4) + v_row) * 128 + (wn << 5) + v_cb);
                ldsm4t(bhf, sb + 32768 + off);
                ldsm4t(blf, sb + 40960 + off);
            }
            #pragma unroll
            for (int mi = 0; mi < 4; mi++)
                #pragma unroll
                for (int ni = 0; ni < 2; ni++) {
                    const uint32_t* bh2 = &bhf[ni << 1];
                    const uint32_t* bl2 = &blf[ni << 1];
                    mma16816(acc[mi][ni], ahf[mi], bh2);
                    mma16816(acc[mi][ni], alf[mi], bh2);
                    mma16816(acc[mi][ni], ahf[mi], bl2);
                }
        }
    }
    // epilogue -> g_Chi/g_Clo [m][1024]
    #pragma unroll
    for (int mi = 0; mi < 4; mi++)
        #pragma unroll
        for (int ni = 0; ni < 2; ni++)
            #pragma unroll
            for (int half = 0; half < 2; half++) {
                int r = (wm << 6) + (mi << 4) + g + half * 8;
                int c = (h << 6) + (wn << 4) + (ni << 3) + (tq << 1);
                float v0 = acc[mi][ni][half * 2], v1 = acc[mi][ni][half * 2 + 1];
                uint32_t lo, hi = pk2(v0, v1, lo);
                size_t o = ((size_t)(b * 2048 + q0 + r)) * 1024 + c;
                *(uint32_t*)(g_Chi + o) = hi;
                *(uint32_t*)(g_Clo + o) = lo;
            }
}

// ---------------- launch --------------------------------------------------------
#define PROJ_SMEM 65536
#define SC_SMEM   67584
#define CTX_SMEM  49664

extern "C" void kernel_launch(void* const* d_in, const int* in_sizes, int n_in,
                              void* d_out, int out_size) {
    const float* hs   = (const float*)d_in[0];
    const int*   mask = (const int*)d_in[1];
    const float* Wq   = (const float*)d_in[2];
    const float* Wk   = (const float*)d_in[3];
    const float* Wv   = (const float*)d_in[4];
    const float* Wo   = (const float*)d_in[5];
    const float* rb   = (const float*)d_in[6];
    float* out  = (float*)d_out;
    float* attn = out + 4194304;

    static int configured = 0;
    cudaFuncSetAttribute(proj_gemm,   cudaFuncAttributeMaxDynamicSharedMemorySize, PROJ_SMEM);
    cudaFuncSetAttribute(attn_scores, cudaFuncAttributeMaxDynamicSharedMemorySize, SC_SMEM);
    cudaFuncSetAttribute(attn_ctx,    cudaFuncAttributeMaxDynamicSharedMemorySize, CTX_SMEM);
    (void)configured;

    bias_init<<<16, 256>>>(rb);
    split_x<<<4096, 256>>>(hs);
    wsplit<<<dim3(32, 32, 4), dim3(32, 8)>>>(Wq, Wk, Wv, Wo);

    proj_gemm<<<dim3(8, 32), 256, PROJ_SMEM>>>(nullptr, 0);
    proj_gemm<<<dim3(8, 32), 256, PROJ_SMEM>>>(nullptr, 1);
    proj_gemm<<<dim3(8, 32), 256, PROJ_SMEM>>>(nullptr, 2);

    attn_scores<<<dim3(16, 32), 256, SC_SMEM>>>(mask, attn);
    attn_ctx<<<dim3(16, 32), 256, CTX_SMEM>>>(attn);

    proj_gemm<<<dim3(8, 32), 256, PROJ_SMEM>>>(out, 3);
}

// round 7
// speedup vs baseline: 2.1674x; 1.2037x over previous
#include <cuda_runtime.h>
#include <cuda_bf16.h>
#include <cstdint>

// ---------------- scratch (static device arrays; no cudaMalloc) -------------
__device__ __align__(16) __nv_bfloat16 g_Xhi[4194304], g_Xlo[4194304];
__device__ __align__(16) __nv_bfloat16 g_Whi[4][1048576], g_Wlo[4][1048576];
__device__ __align__(16) __nv_bfloat16 g_Qhi[4194304], g_Qlo[4194304];
__device__ __align__(16) __nv_bfloat16 g_Khi[4194304], g_Klo[4194304];
__device__ __align__(16) __nv_bfloat16 g_Vhi[4194304], g_Vlo[4194304]; // [bh][s][dkv]
__device__ __align__(16) __nv_bfloat16 g_Chi[4194304], g_Clo[4194304]; // [m][1024]
__device__ float g_rowsum[65536];
__device__ float g_bias[16 * 4096];

// ---------------- helpers -----------------------------------------------------
__device__ __forceinline__ uint32_t smem_u32(const void* p) {
    uint32_t a;
    asm("{ .reg .u64 t; cvta.to.shared.u64 t, %1; cvt.u32.u64 %0, t; }" : "=r"(a) : "l"(p));
    return a;
}
__device__ __forceinline__ uint32_t swz(uint32_t off) { return off ^ ((off >> 3) & 0x70); }

__device__ __forceinline__ void cpa16(uint32_t saddr, const void* g) {
    asm volatile("cp.async.cg.shared.global [%0], [%1], 16;" :: "r"(saddr), "l"(g));
}
#define CP_COMMIT() asm volatile("cp.async.commit_group;" ::: "memory")
#define CP_WAIT1()  asm volatile("cp.async.wait_group 1;" ::: "memory")
#define CP_WAIT0()  asm volatile("cp.async.wait_group 0;" ::: "memory")

__device__ __forceinline__ void ldsm4(uint32_t* r, uint32_t addr) {
    asm volatile("ldmatrix.sync.aligned.m8n8.x4.shared.b16 {%0,%1,%2,%3}, [%4];"
        : "=r"(r[0]), "=r"(r[1]), "=r"(r[2]), "=r"(r[3]) : "r"(addr));
}
__device__ __forceinline__ void ldsm4t(uint32_t* r, uint32_t addr) {
    asm volatile("ldmatrix.sync.aligned.m8n8.x4.trans.shared.b16 {%0,%1,%2,%3}, [%4];"
        : "=r"(r[0]), "=r"(r[1]), "=r"(r[2]), "=r"(r[3]) : "r"(addr));
}
__device__ __forceinline__ void mma16816(float* d, const uint32_t* a, const uint32_t* b) {
    asm volatile("mma.sync.aligned.m16n8k16.row.col.f32.bf16.bf16.f32 "
        "{%0,%1,%2,%3}, {%4,%5,%6,%7}, {%8,%9}, {%0,%1,%2,%3};"
        : "+f"(d[0]), "+f"(d[1]), "+f"(d[2]), "+f"(d[3])
        : "r"(a[0]), "r"(a[1]), "r"(a[2]), "r"(a[3]), "r"(b[0]), "r"(b[1]));
}
__device__ __forceinline__ uint32_t pk2(float a, float b, uint32_t& lo) {
    __nv_bfloat162 h, l;
    h.x = __float2bfloat16_rn(a); h.y = __float2bfloat16_rn(b);
    l.x = __float2bfloat16_rn(a - __bfloat162float(h.x));
    l.y = __float2bfloat16_rn(b - __bfloat162float(h.y));
    lo = *(uint32_t*)&l;
    return *(uint32_t*)&h;
}

// ---------------- prep kernels -------------------------------------------------
__global__ void bias_init(const float* __restrict__ rel_bias) {
    int d = blockIdx.x * 256 + threadIdx.x;
    if (d >= 4096) return;
    int n = -(d - 2048);
    int ret = 0;
    if (n < 0) { ret = 16; n = -n; }
    int bucket;
    if      (n <  8) bucket = n;
    else if (n < 12) bucket = 8;
    else if (n < 16) bucket = 9;
    else if (n < 23) bucket = 10;
    else if (n < 32) bucket = 11;
    else if (n < 46) bucket = 12;
    else if (n < 64) bucket = 13;
    else if (n < 91) bucket = 14;
    else             bucket = 15;
    bucket += ret;
    #pragma unroll
    for (int h = 0; h < 16; h++)
        g_bias[h * 4096 + d] = rel_bias[bucket * 16 + h];
}

__global__ void split_x(const float* __restrict__ src) {
    size_t i = ((size_t)blockIdx.x * 256 + threadIdx.x) * 4;
    float4 v = *(const float4*)(src + i);
    float x[4] = {v.x, v.y, v.z, v.w};
    #pragma unroll
    for (int j = 0; j < 4; j++) {
        __nv_bfloat16 hh = __float2bfloat16_rn(x[j]);
        g_Xhi[i + j] = hh;
        g_Xlo[i + j] = __float2bfloat16_rn(x[j] - __bfloat162float(hh));
    }
}

__global__ void wsplit(const float* __restrict__ W0, const float* __restrict__ W1,
                       const float* __restrict__ W2, const float* __restrict__ W3) {
    __shared__ float tile[32][33];
    const float* W = blockIdx.z == 0 ? W0 : blockIdx.z == 1 ? W1 : blockIdx.z == 2 ? W2 : W3;
    int n0 = blockIdx.x * 32, k0 = blockIdx.y * 32;
    int tx = threadIdx.x, ty = threadIdx.y;
    #pragma unroll
    for (int j = 0; j < 4; j++)
        tile[ty + j * 8][tx] = W[(size_t)(k0 + ty + j * 8) * 1024 + n0 + tx];
    __syncthreads();
    #pragma unroll
    for (int j = 0; j < 4; j++) {
        float x = tile[tx][ty + j * 8];
        __nv_bfloat16 hh = __float2bfloat16_rn(x);
        size_t o = (size_t)(n0 + ty + j * 8) * 1024 + k0 + tx;     // [n][k]
        g_Whi[blockIdx.z][o] = hh;
        g_Wlo[blockIdx.z][o] = __float2bfloat16_rn(x - __bfloat162float(hh));
    }
}

// ---------------- unified 128x128 HMMA GEMM, 2-stage cp.async pipeline ---------
// qkv=1: mode = blockIdx.z (Q/K/V).  qkv=0: mode 3 (ctx @ Wo -> out fp32).
__global__ __launch_bounds__(256) void proj_gemm(float* __restrict__ outp, int qkv) {
    extern __shared__ __align__(1024) char smx[];
    const uint32_t sb = smem_u32(smx);
    const int t = threadIdx.x, lane = t & 31, wid = t >> 5;
    const int wm = wid >> 2, wn = wid & 3;
    const int m0 = blockIdx.y << 7, n0 = blockIdx.x << 7;
    const int mode = qkv ? (int)blockIdx.z : 3;
    const __nv_bfloat16* Ah = (mode == 3) ? g_Chi : g_Xhi;
    const __nv_bfloat16* Al = (mode == 3) ? g_Clo : g_Xlo;
    const __nv_bfloat16* Bh = g_Whi[mode];
    const __nv_bfloat16* Bl = g_Wlo[mode];

    auto issue = [&](int kc) {
        const int kb = kc << 6;
        const uint32_t stb = sb + (uint32_t)(kc & 1) * 65536;
        #pragma unroll
        for (int i = 0; i < 4; i++) {
            int idx = t + (i << 8);
            int row = idx >> 3, ge = (idx & 7) << 3;
            uint32_t so = swz(row * 128 + (ge << 1));
            size_t goa = (size_t)(m0 + row) * 1024 + kb + ge;
            size_t gob = (size_t)(n0 + row) * 1024 + kb + ge;
            cpa16(stb + so,         Ah + goa);
            cpa16(stb + 16384 + so, Al + goa);
            cpa16(stb + 32768 + so, Bh + gob);
            cpa16(stb + 49152 + so, Bl + gob);
        }
        CP_COMMIT();
    };

    const uint32_t a_row = (lane & 7) + ((lane >> 3) & 1) * 8;
    const uint32_t a_kb  = (lane >> 4) * 16;
    const uint32_t b_row = (lane & 7) + (lane >> 4) * 8;
    const uint32_t b_kb  = ((lane >> 3) & 1) * 16;

    float acc[4][4][4] = {};
    issue(0);
    for (int kc = 0; kc < 16; kc++) {
        if (kc + 1 < 16) { issue(kc + 1); CP_WAIT1(); }
        else             { CP_WAIT0(); }
        __syncthreads();
        const uint32_t stb = sb + (uint32_t)(kc & 1) * 65536;
        #pragma unroll
        for (int ki = 0; ki < 4; ki++) {
            uint32_t ahf[4][4], alf[4][4], bhf[2][4], blf[2][4];
            #pragma unroll
            for (int mi = 0; mi < 4; mi++) {
                uint32_t off = swz(((wm << 6) + (mi << 4) + a_row) * 128 + (ki << 5) + a_kb);
                ldsm4(ahf[mi], stb + off);
                ldsm4(alf[mi], stb + 16384 + off);
            }
            #pragma unroll
            for (int nh = 0; nh < 2; nh++) {
                uint32_t off = swz(((wn << 5) + (nh << 4) + b_row) * 128 + (ki << 5) + b_kb);
                ldsm4(bhf[nh], stb + 32768 + off);
                ldsm4(blf[nh], stb + 49152 + off);
            }
            #pragma unroll
            for (int mi = 0; mi < 4; mi++)
                #pragma unroll
                for (int ni = 0; ni < 4; ni++) {
                    const uint32_t* bh2 = &bhf[ni >> 1][(ni & 1) << 1];
                    const uint32_t* bl2 = &blf[ni >> 1][(ni & 1) << 1];
                    mma16816(acc[mi][ni], ahf[mi], bh2);
                    mma16816(acc[mi][ni], alf[mi], bh2);
                    mma16816(acc[mi][ni], ahf[mi], bl2);
                }
        }
        __syncthreads();
    }

    const int g = lane >> 2, tq = lane & 3;
    #pragma unroll
    for (int mi = 0; mi < 4; mi++) {
        #pragma unroll
        for (int ni = 0; ni < 4; ni++) {
            #pragma unroll
            for (int half = 0; half < 2; half++) {
                int r = (wm << 6) + (mi << 4) + g + half * 8;
                int c = (wn << 5) + (ni << 3) + (tq << 1);
                float v0 = acc[mi][ni][half * 2], v1 = acc[mi][ni][half * 2 + 1];
                int m = m0 + r, n = n0 + c;
                if (mode == 3) {
                    *(float2*)&outp[(size_t)m * 1024 + n] = make_float2(v0, v1);
                } else {
                    uint32_t lo, hi = pk2(v0, v1, lo);
                    int b = m >> 11, s = m & 2047, hd = n >> 6, dk = n & 63;
                    size_t o = (((size_t)(b * 16 + hd) * 2048) + s) * 64 + dk;
                    __nv_bfloat16* dh = (mode == 0) ? g_Qhi : (mode == 1) ? g_Khi : g_Vhi;
                    __nv_bfloat16* dl = (mode == 0) ? g_Qlo : (mode == 1) ? g_Klo : g_Vlo;
                    *(uint32_t*)(dh + o) = hi;
                    *(uint32_t*)(dl + o) = lo;
                }
            }
        }
    }
}

// ---------------- scores: attn = exp(QK/8 + bias), masked->0, rowsums ----------
// smem: QH 0, QL 16384 | K stage0 {KH 32768, KL 49152} stage1 {65536, 81920}
//       biasW stage s @ 98304 + s*1024 (255 fl) | maskS s @ 100352 + s*512 | rowsm @ 101376
__global__ __launch_bounds__(256) void attn_scores(const int* __restrict__ mask,
                                                   float* __restrict__ attn) {
    extern __shared__ __align__(1024) char smx[];
    const uint32_t sb = smem_u32(smx);
    float* rowsm = (float*)(smx + 101376);
    const int t = threadIdx.x, lane = t & 31, wid = t >> 5;
    const int wm = wid >> 2, wn = wid & 3;
    const int q0 = blockIdx.x << 7, bh = blockIdx.y, b = bh >> 4, h = bh & 15;
    const int g = lane >> 2, tq = lane & 3;

    // persistent Q tiles
    #pragma unroll
    for (int i = 0; i < 4; i++) {
        int idx = t + (i << 8);
        int row = idx >> 3, ge = (idx & 7) << 3;
        uint32_t so = swz(row * 128 + (ge << 1));
        size_t go = ((size_t)bh * 2048 + q0 + row) * 64 + ge;
        *(uint4*)(smx + so)         = *(const uint4*)(g_Qhi + go);
        *(uint4*)(smx + 16384 + so) = *(const uint4*)(g_Qlo + go);
    }
    if (t < 128) rowsm[t] = 0.f;

    auto issue = [&](int kt) {
        const int k0 = kt << 7, s = kt & 1;
        const uint32_t stb = sb + 32768 + (uint32_t)s * 32768;
        #pragma unroll
        for (int i = 0; i < 4; i++) {
            int idx = t + (i << 8);
            int row = idx >> 3, ge = (idx & 7) << 3;
            uint32_t so = swz(row * 128 + (ge << 1));
            size_t go = ((size_t)bh * 2048 + k0 + row) * 64 + ge;
            cpa16(stb + so,         g_Khi + go);
            cpa16(stb + 16384 + so, g_Klo + go);
        }
        CP_COMMIT();
        float* bw = (float*)(smx + 98304 + s * 1024);
        int*   ms = (int*)(smx + 100352 + s * 512);
        if (t < 255) bw[t] = g_bias[h * 4096 + (k0 - q0 + 1921) + t];
        if (t < 128) ms[t] = mask[b * 2048 + k0 + t];
    };

    const uint32_t a_row = (lane & 7) + ((lane >> 3) & 1) * 8;
    const uint32_t a_kb  = (lane >> 4) * 16;
    const uint32_t b_row = (lane & 7) + (lane >> 4) * 8;
    const uint32_t b_kb  = ((lane >> 3) & 1) * 16;

    float rowpart[4][2] = {};
    issue(0);
    for (int kt = 0; kt < 16; kt++) {
        if (kt + 1 < 16) { issue(kt + 1); CP_WAIT1(); }
        else             { CP_WAIT0(); }
        __syncthreads();
        const int k0 = kt << 7, s = kt & 1;
        const uint32_t kb_base = sb + 32768 + (uint32_t)s * 32768;
        const float* biasW = (const float*)(smx + 98304 + s * 1024);
        const int*   maskS = (const int*)(smx + 100352 + s * 512);

        float acc[4][4][4] = {};
        #pragma unroll
        for (int ki = 0; ki < 4; ki++) {
            uint32_t ahf[4][4], alf[4][4], bhf[2][4], blf[2][4];
            #pragma unroll
            for (int mi = 0; mi < 4; mi++) {
                uint32_t off = swz(((wm << 6) + (mi << 4) + a_row) * 128 + (ki << 5) + a_kb);
                ldsm4(ahf[mi], sb + off);
                ldsm4(alf[mi], sb + 16384 + off);
            }
            #pragma unroll
            for (int nh = 0; nh < 2; nh++) {
                uint32_t off = swz(((wn << 5) + (nh << 4) + b_row) * 128 + (ki << 5) + b_kb);
                ldsm4(bhf[nh], kb_base + off);
                ldsm4(blf[nh], kb_base + 16384 + off);
            }
            #pragma unroll
            for (int mi = 0; mi < 4; mi++)
                #pragma unroll
                for (int ni = 0; ni < 4; ni++) {
                    const uint32_t* bh2 = &bhf[ni >> 1][(ni & 1) << 1];
                    const uint32_t* bl2 = &blf[ni >> 1][(ni & 1) << 1];
                    mma16816(acc[mi][ni], ahf[mi], bh2);
                    mma16816(acc[mi][ni], alf[mi], bh2);
                    mma16816(acc[mi][ni], ahf[mi], bl2);
                }
        }
        #pragma unroll
        for (int mi = 0; mi < 4; mi++) {
            #pragma unroll
            for (int half = 0; half < 2; half++) {
                int r = (wm << 6) + (mi << 4) + g + half * 8;
                float rp = 0.f;
                #pragma unroll
                for (int ni = 0; ni < 4; ni++) {
                    int c = (wn << 5) + (ni << 3) + (tq << 1);
                    float s0 = fmaf(acc[mi][ni][half * 2],     0.125f, biasW[c - r + 127]);
                    float s1 = fmaf(acc[mi][ni][half * 2 + 1], 0.125f, biasW[c + 1 - r + 127]);
                    float e0 = maskS[c]     ? __expf(s0) : 0.f;
                    float e1 = maskS[c + 1] ? __expf(s1) : 0.f;
                    rp += e0 + e1;
                    *(float2*)&attn[((size_t)bh * 2048 + q0 + r) * 2048 + k0 + c] =
                        make_float2(e0, e1);
                }
                rowpart[mi][half] += rp;
            }
        }
        __syncthreads();
    }
    #pragma unroll
    for (int mi = 0; mi < 4; mi++)
        #pragma unroll
        for (int half = 0; half < 2; half++) {
            float v = rowpart[mi][half];
            v += __shfl_xor_sync(0xffffffffu, v, 1);
            v += __shfl_xor_sync(0xffffffffu, v, 2);
            if (tq == 0)
                atomicAdd(&rowsm[(wm << 6) + (mi << 4) + g + half * 8], v);
        }
    __syncthreads();
    if (t < 128) g_rowsum[bh * 2048 + q0 + t] = rowsm[t];
}

// ---------------- ctx: normalize attn in place (final weights), ctx = P @ V ----
// smem: PH 0, PL 16384 | V stage0 {VH 32768, VL 40960} stage1 {49152, 57344} | rinv 65536
__global__ __launch_bounds__(256) void attn_ctx(float* __restrict__ attn) {
    extern __shared__ __align__(1024) char smx[];
    const uint32_t sb = smem_u32(smx);
    float* rinv = (float*)(smx + 65536);
    const int t = threadIdx.x, lane = t & 31, wid = t >> 5;
    const int wm = wid >> 2, wn = wid & 3;
    const int q0 = blockIdx.x << 7, bh = blockIdx.y, b = bh >> 4, h = bh & 15;
    const int g = lane >> 2, tq = lane & 3;
    if (t < 128) rinv[t] = 1.0f / g_rowsum[bh * 2048 + q0 + t];
    __syncthreads();   // rinv visible to ALL threads before first normalize (R6 bug fix)

    auto issue_v = [&](int kc) {
        const int k0 = kc << 6, s = kc & 1;
        const uint32_t stb = sb + 32768 + (uint32_t)s * 16384;
        #pragma unroll
        for (int i = 0; i < 2; i++) {
            int idx = t + (i << 8);
            int row = idx >> 3, ge = (idx & 7) << 3;
            uint32_t so = swz(row * 128 + (ge << 1));
            size_t go = ((size_t)bh * 2048 + k0 + row) * 64 + ge;
            cpa16(stb + so,        g_Vhi + go);
            cpa16(stb + 8192 + so, g_Vlo + go);
        }
        CP_COMMIT();
    };

    const uint32_t a_row = (lane & 7) + ((lane >> 3) & 1) * 8;
    const uint32_t a_kb  = (lane >> 4) * 16;
    const uint32_t v_row = (lane & 7) + ((lane >> 3) & 1) * 8;
    const uint32_t v_cb  = (lane >> 4) * 16;

    float acc[4][2][4] = {};
    issue_v(0);
    for (int kc = 0; kc < 32; kc++) {
        const int k0 = kc << 6;
        if (kc + 1 < 32) issue_v(kc + 1);
        // P: load attn, normalize, writeback (final weights), split to smem
        #pragma unroll
        for (int i = 0; i < 8; i++) {
            int idx = t + (i << 8);
            int row = idx >> 4, c4 = (idx & 15) << 2;
            size_t ga = ((size_t)bh * 2048 + q0 + row) * 2048 + k0 + c4;
            float4 v = *(const float4*)&attn[ga];
            float ri = rinv[row];
            v.x *= ri; v.y *= ri; v.z *= ri; v.w *= ri;
            *(float4*)&attn[ga] = v;
            uint32_t l0, h0 = pk2(v.x, v.y, l0);
            uint32_t l1, h1 = pk2(v.z, v.w, l1);
            uint32_t so = swz(row * 128 + (c4 << 1));
            *(uint2*)(smx + so)         = make_uint2(h0, h1);
            *(uint2*)(smx + 16384 + so) = make_uint2(l0, l1);
        }
        if (kc + 1 < 32) { CP_WAIT1(); } else { CP_WAIT0(); }
        __syncthreads();
        const uint32_t vb = sb + 32768 + (uint32_t)(kc & 1) * 16384;
        #pragma unroll
        for (int ki = 0; ki < 4; ki++) {
            uint32_t ahf[4][4], alf[4][4], bhf[4], blf[4];
            #pragma unroll
            for (int mi = 0; mi < 4; mi++) {
                uint32_t off = swz(((wm << 6) + (mi << 4) + a_row) * 128 + (ki << 5) + a_kb);
                ldsm4(ahf[mi], sb + off);
                ldsm4(alf[mi], sb + 16384 + off);
            }
            {
                uint32_t off = swz(((ki << 4) + v_row) * 128 + (wn << 5) + v_cb);
                ldsm4t(bhf, vb + off);
                ldsm4t(blf, vb + 8192 + off);
            }
            #pragma unroll
            for (int mi = 0; mi < 4; mi++)
                #pragma unroll
                for (int ni = 0; ni < 2; ni++) {
                    const uint32_t* bh2 = &bhf[ni << 1];
                    const uint32_t* bl2 = &blf[ni << 1];
                    mma16816(acc[mi][ni], ahf[mi], bh2);
                    mma16816(acc[mi][ni], alf[mi], bh2);
                    mma16816(acc[mi][ni], ahf[mi], bl2);
                }
        }
        __syncthreads();
    }
    #pragma unroll
    for (int mi = 0; mi < 4; mi++)
        #pragma unroll
        for (int ni = 0; ni < 2; ni++)
            #pragma unroll
            for (int half = 0; half < 2; half++) {
                int r = (wm << 6) + (mi << 4) + g + half * 8;
                int c = (h << 6) + (wn << 4) + (ni << 3) + (tq << 1);
                float v0 = acc[mi][ni][half * 2], v1 = acc[mi][ni][half * 2 + 1];
                uint32_t lo, hi = pk2(v0, v1, lo);
                size_t o = ((size_t)(b * 2048 + q0 + r)) * 1024 + c;
                *(uint32_t*)(g_Chi + o) = hi;
                *(uint32_t*)(g_Clo + o) = lo;
            }
}

// ---------------- launch --------------------------------------------------------
#define PROJ_SMEM 131072
#define SC_SMEM   102400
#define CTX_SMEM  66560

extern "C" void kernel_launch(void* const* d_in, const int* in_sizes, int n_in,
                              void* d_out, int out_size) {
    const float* hs   = (const float*)d_in[0];
    const int*   mask = (const int*)d_in[1];
    const float* Wq   = (const float*)d_in[2];
    const float* Wk   = (const float*)d_in[3];
    const float* Wv   = (const float*)d_in[4];
    const float* Wo   = (const float*)d_in[5];
    const float* rb   = (const float*)d_in[6];
    float* out  = (float*)d_out;
    float* attn = out + 4194304;

    cudaFuncSetAttribute(proj_gemm,   cudaFuncAttributeMaxDynamicSharedMemorySize, PROJ_SMEM);
    cudaFuncSetAttribute(attn_scores, cudaFuncAttributeMaxDynamicSharedMemorySize, SC_SMEM);
    cudaFuncSetAttribute(attn_ctx,    cudaFuncAttributeMaxDynamicSharedMemorySize, CTX_SMEM);

    bias_init<<<16, 256>>>(rb);
    split_x<<<4096, 256>>>(hs);
    wsplit<<<dim3(32, 32, 4), dim3(32, 8)>>>(Wq, Wk, Wv, Wo);

    proj_gemm<<<dim3(8, 32, 3), 256, PROJ_SMEM>>>(nullptr, 1);   // Q,K,V fused

    attn_scores<<<dim3(16, 32), 256, SC_SMEM>>>(mask, attn);
    attn_ctx<<<dim3(16, 32), 256, CTX_SMEM>>>(attn);

    proj_gemm<<<dim3(8, 32, 1), 256, PROJ_SMEM>>>(out, 0);       // ctx @ Wo
}

// round 8
// speedup vs baseline: 2.3598x; 1.0887x over previous
#include <cuda_runtime.h>
#include <cuda_bf16.h>
#include <cstdint>

// ---------------- scratch (static device arrays; no cudaMalloc) -------------
__device__ __align__(16) __nv_bfloat16 g_Xhi[4194304], g_Xlo[4194304];
__device__ __align__(16) __nv_bfloat16 g_Whi[4][1048576], g_Wlo[4][1048576];
__device__ __align__(16) __nv_bfloat16 g_Qhi[4194304], g_Qlo[4194304];
__device__ __align__(16) __nv_bfloat16 g_Khi[4194304], g_Klo[4194304];
__device__ __align__(16) __nv_bfloat16 g_Vhi[4194304], g_Vlo[4194304]; // [bh][s][dkv]
__device__ __align__(16) __nv_bfloat16 g_Chi[4194304], g_Clo[4194304]; // [m][1024]
__device__ float g_bias[16 * 4096];

// ---------------- helpers -----------------------------------------------------
__device__ __forceinline__ uint32_t smem_u32(const void* p) {
    uint32_t a;
    asm("{ .reg .u64 t; cvta.to.shared.u64 t, %1; cvt.u32.u64 %0, t; }" : "=r"(a) : "l"(p));
    return a;
}
__device__ __forceinline__ uint32_t swz(uint32_t off) { return off ^ ((off >> 3) & 0x70); }

__device__ __forceinline__ void cpa16(uint32_t saddr, const void* g) {
    asm volatile("cp.async.cg.shared.global [%0], [%1], 16;" :: "r"(saddr), "l"(g));
}
#define CP_COMMIT() asm volatile("cp.async.commit_group;" ::: "memory")
#define CP_WAIT1()  asm volatile("cp.async.wait_group 1;" ::: "memory")
#define CP_WAIT0()  asm volatile("cp.async.wait_group 0;" ::: "memory")

__device__ __forceinline__ void ldsm4(uint32_t* r, uint32_t addr) {
    asm volatile("ldmatrix.sync.aligned.m8n8.x4.shared.b16 {%0,%1,%2,%3}, [%4];"
        : "=r"(r[0]), "=r"(r[1]), "=r"(r[2]), "=r"(r[3]) : "r"(addr));
}
__device__ __forceinline__ void ldsm4t(uint32_t* r, uint32_t addr) {
    asm volatile("ldmatrix.sync.aligned.m8n8.x4.trans.shared.b16 {%0,%1,%2,%3}, [%4];"
        : "=r"(r[0]), "=r"(r[1]), "=r"(r[2]), "=r"(r[3]) : "r"(addr));
}
__device__ __forceinline__ void mma16816(float* d, const uint32_t* a, const uint32_t* b) {
    asm volatile("mma.sync.aligned.m16n8k16.row.col.f32.bf16.bf16.f32 "
        "{%0,%1,%2,%3}, {%4,%5,%6,%7}, {%8,%9}, {%0,%1,%2,%3};"
        : "+f"(d[0]), "+f"(d[1]), "+f"(d[2]), "+f"(d[3])
        : "r"(a[0]), "r"(a[1]), "r"(a[2]), "r"(a[3]), "r"(b[0]), "r"(b[1]));
}
__device__ __forceinline__ uint32_t pk2(float a, float b, uint32_t& lo) {
    __nv_bfloat162 h, l;
    h.x = __float2bfloat16_rn(a); h.y = __float2bfloat16_rn(b);
    l.x = __float2bfloat16_rn(a - __bfloat162float(h.x));
    l.y = __float2bfloat16_rn(b - __bfloat162float(h.y));
    lo = *(uint32_t*)&l;
    return *(uint32_t*)&h;
}

// ---------------- prep kernels -------------------------------------------------
__global__ void bias_init(const float* __restrict__ rel_bias) {
    int d = blockIdx.x * 256 + threadIdx.x;
    if (d >= 4096) return;
    int n = -(d - 2048);
    int ret = 0;
    if (n < 0) { ret = 16; n = -n; }
    int bucket;
    if      (n <  8) bucket = n;
    else if (n < 12) bucket = 8;
    else if (n < 16) bucket = 9;
    else if (n < 23) bucket = 10;
    else if (n < 32) bucket = 11;
    else if (n < 46) bucket = 12;
    else if (n < 64) bucket = 13;
    else if (n < 91) bucket = 14;
    else             bucket = 15;
    bucket += ret;
    #pragma unroll
    for (int h = 0; h < 16; h++)
        g_bias[h * 4096 + d] = rel_bias[bucket * 16 + h];
}

__global__ void split_x(const float* __restrict__ src) {
    size_t i = ((size_t)blockIdx.x * 256 + threadIdx.x) * 4;
    float4 v = *(const float4*)(src + i);
    float x[4] = {v.x, v.y, v.z, v.w};
    #pragma unroll
    for (int j = 0; j < 4; j++) {
        __nv_bfloat16 hh = __float2bfloat16_rn(x[j]);
        g_Xhi[i + j] = hh;
        g_Xlo[i + j] = __float2bfloat16_rn(x[j] - __bfloat162float(hh));
    }
}

__global__ void wsplit(const float* __restrict__ W0, const float* __restrict__ W1,
                       const float* __restrict__ W2, const float* __restrict__ W3) {
    __shared__ float tile[32][33];
    const float* W = blockIdx.z == 0 ? W0 : blockIdx.z == 1 ? W1 : blockIdx.z == 2 ? W2 : W3;
    int n0 = blockIdx.x * 32, k0 = blockIdx.y * 32;
    int tx = threadIdx.x, ty = threadIdx.y;
    #pragma unroll
    for (int j = 0; j < 4; j++)
        tile[ty + j * 8][tx] = W[(size_t)(k0 + ty + j * 8) * 1024 + n0 + tx];
    __syncthreads();
    #pragma unroll
    for (int j = 0; j < 4; j++) {
        float x = tile[tx][ty + j * 8];
        __nv_bfloat16 hh = __float2bfloat16_rn(x);
        size_t o = (size_t)(n0 + ty + j * 8) * 1024 + k0 + tx;     // [n][k]
        g_Whi[blockIdx.z][o] = hh;
        g_Wlo[blockIdx.z][o] = __float2bfloat16_rn(x - __bfloat162float(hh));
    }
}

// ---------------- unified 128x128 HMMA GEMM, 2-stage cp.async pipeline ---------
__global__ __launch_bounds__(256) void proj_gemm(float* __restrict__ outp, int qkv) {
    extern __shared__ __align__(1024) char smx[];
    const uint32_t sb = smem_u32(smx);
    const int t = threadIdx.x, lane = t & 31, wid = t >> 5;
    const int wm = wid >> 2, wn = wid & 3;
    const int m0 = blockIdx.y << 7, n0 = blockIdx.x << 7;
    const int mode = qkv ? (int)blockIdx.z : 3;
    const __nv_bfloat16* Ah = (mode == 3) ? g_Chi : g_Xhi;
    const __nv_bfloat16* Al = (mode == 3) ? g_Clo : g_Xlo;
    const __nv_bfloat16* Bh = g_Whi[mode];
    const __nv_bfloat16* Bl = g_Wlo[mode];

    auto issue = [&](int kc) {
        const int kb = kc << 6;
        const uint32_t stb = sb + (uint32_t)(kc & 1) * 65536;
        #pragma unroll
        for (int i = 0; i < 4; i++) {
            int idx = t + (i << 8);
            int row = idx >> 3, ge = (idx & 7) << 3;
            uint32_t so = swz(row * 128 + (ge << 1));
            size_t goa = (size_t)(m0 + row) * 1024 + kb + ge;
            size_t gob = (size_t)(n0 + row) * 1024 + kb + ge;
            cpa16(stb + so,         Ah + goa);
            cpa16(stb + 16384 + so, Al + goa);
            cpa16(stb + 32768 + so, Bh + gob);
            cpa16(stb + 49152 + so, Bl + gob);
        }
        CP_COMMIT();
    };

    const uint32_t a_row = (lane & 7) + ((lane >> 3) & 1) * 8;
    const uint32_t a_kb  = (lane >> 4) * 16;
    const uint32_t b_row = (lane & 7) + (lane >> 4) * 8;
    const uint32_t b_kb  = ((lane >> 3) & 1) * 16;

    float acc[4][4][4] = {};
    issue(0);
    for (int kc = 0; kc < 16; kc++) {
        if (kc + 1 < 16) { issue(kc + 1); CP_WAIT1(); }
        else             { CP_WAIT0(); }
        __syncthreads();
        const uint32_t stb = sb + (uint32_t)(kc & 1) * 65536;
        #pragma unroll
        for (int ki = 0; ki < 4; ki++) {
            uint32_t ahf[4][4], alf[4][4], bhf[2][4], blf[2][4];
            #pragma unroll
            for (int mi = 0; mi < 4; mi++) {
                uint32_t off = swz(((wm << 6) + (mi << 4) + a_row) * 128 + (ki << 5) + a_kb);
                ldsm4(ahf[mi], stb + off);
                ldsm4(alf[mi], stb + 16384 + off);
            }
            #pragma unroll
            for (int nh = 0; nh < 2; nh++) {
                uint32_t off = swz(((wn << 5) + (nh << 4) + b_row) * 128 + (ki << 5) + b_kb);
                ldsm4(bhf[nh], stb + 32768 + off);
                ldsm4(blf[nh], stb + 49152 + off);
            }
            #pragma unroll
            for (int mi = 0; mi < 4; mi++)
                #pragma unroll
                for (int ni = 0; ni < 4; ni++) {
                    const uint32_t* bh2 = &bhf[ni >> 1][(ni & 1) << 1];
                    const uint32_t* bl2 = &blf[ni >> 1][(ni & 1) << 1];
                    mma16816(acc[mi][ni], ahf[mi], bh2);
                    mma16816(acc[mi][ni], alf[mi], bh2);
                    mma16816(acc[mi][ni], ahf[mi], bl2);
                }
        }
        __syncthreads();
    }

    const int g = lane >> 2, tq = lane & 3;
    #pragma unroll
    for (int mi = 0; mi < 4; mi++) {
        #pragma unroll
        for (int ni = 0; ni < 4; ni++) {
            #pragma unroll
            for (int half = 0; half < 2; half++) {
                int r = (wm << 6) + (mi << 4) + g + half * 8;
                int c = (wn << 5) + (ni << 3) + (tq << 1);
                float v0 = acc[mi][ni][half * 2], v1 = acc[mi][ni][half * 2 + 1];
                int m = m0 + r, n = n0 + c;
                if (mode == 3) {
                    *(float2*)&outp[(size_t)m * 1024 + n] = make_float2(v0, v1);
                } else {
                    uint32_t lo, hi = pk2(v0, v1, lo);
                    int b = m >> 11, s = m & 2047, hd = n >> 6, dk = n & 63;
                    size_t o = (((size_t)(b * 16 + hd) * 2048) + s) * 64 + dk;
                    __nv_bfloat16* dh = (mode == 0) ? g_Qhi : (mode == 1) ? g_Khi : g_Vhi;
                    __nv_bfloat16* dl = (mode == 0) ? g_Qlo : (mode == 1) ? g_Klo : g_Vlo;
                    *(uint32_t*)(dh + o) = hi;
                    *(uint32_t*)(dl + o) = lo;
                }
            }
        }
    }
}

// ---------------- fused attention: 64q-tile, two-pass softmax + PV -------------
// smem: QH 0 (8K), QL 8192 (8K), rowsm 16384 (64f), rinv 16640 (64f),
//       bias stage s @ 17408+s*1024 (191f), mask s @ 19456+s*512 (128i),
//       K/V stages @ 20480 + s*65536: {KH +0, KL +16K, VH +32K, VL +48K}
//       PV-reduce buffer reuses 20480.. (64KB) after last tile.
__global__ __launch_bounds__(256) void attn_fused(const int* __restrict__ mask,
                                                  float* __restrict__ attn) {
    extern __shared__ __align__(1024) char smx[];
    const uint32_t sb = smem_u32(smx);
    float* rowsm = (float*)(smx + 16384);
    float* rinv  = (float*)(smx + 16640);
    const int t = threadIdx.x, lane = t & 31, wid = t >> 5;
    const int wm = wid >> 2, wn = wid & 3;          // wm 0..1 (q rows), wn 0..3 (k slice)
    const int q0 = blockIdx.x << 6, bh = blockIdx.y, b = bh >> 4, h = bh & 15;
    const int g = lane >> 2, tq = lane & 3;

    // persistent Q tile (64 x 64 dkv), hi/lo
    #pragma unroll
    for (int i = 0; i < 2; i++) {
        int idx = t + (i << 8);
        int row = idx >> 3, ge = (idx & 7) << 3;
        uint32_t so = swz(row * 128 + (ge << 1));
        size_t go = ((size_t)bh * 2048 + q0 + row) * 64 + ge;
        *(uint4*)(smx + so)        = *(const uint4*)(g_Qhi + go);
        *(uint4*)(smx + 8192 + so) = *(const uint4*)(g_Qlo + go);
    }
    if (t < 64) rowsm[t] = 0.f;

    auto issue = [&](int kt, bool withV) {
        const int k0 = kt << 7, s = kt & 1;
        const uint32_t stb = sb + 20480 + (uint32_t)s * 65536;
        #pragma unroll
        for (int i = 0; i < 4; i++) {
            int idx = t + (i << 8);
            int row = idx >> 3, ge = (idx & 7) << 3;
            uint32_t so = swz(row * 128 + (ge << 1));
            size_t go = ((size_t)bh * 2048 + k0 + row) * 64 + ge;
            cpa16(stb + so,         g_Khi + go);
            cpa16(stb + 16384 + so, g_Klo + go);
            if (withV) {
                cpa16(stb + 32768 + so, g_Vhi + go);
                cpa16(stb + 49152 + so, g_Vlo + go);
            }
        }
        CP_COMMIT();
        float* bw = (float*)(smx + 17408 + s * 1024);
        int*   ms = (int*)(smx + 19456 + s * 512);
        if (t < 191) bw[t] = g_bias[h * 4096 + (k0 - q0 + 1985) + t];
        if (t < 128) ms[t] = mask[b * 2048 + k0 + t];
    };

    const uint32_t a_row = (lane & 7) + ((lane >> 3) & 1) * 8;
    const uint32_t a_kb  = (lane >> 4) * 16;
    const uint32_t b_row = (lane & 7) + (lane >> 4) * 8;
    const uint32_t b_kb  = ((lane >> 3) & 1) * 16;

    auto computeS = [&](int s, float acc[2][4][4]) {
        const uint32_t kbb = sb + 20480 + (uint32_t)s * 65536;
        #pragma unroll
        for (int ki = 0; ki < 4; ki++) {
            uint32_t ahf[2][4], alf[2][4], bhf[2][4], blf[2][4];
            #pragma unroll
            for (int mi = 0; mi < 2; mi++) {
                uint32_t off = swz(((wm << 5) + (mi << 4) + a_row) * 128 + (ki << 5) + a_kb);
                ldsm4(ahf[mi], sb + off);
                ldsm4(alf[mi], sb + 8192 + off);
            }
            #pragma unroll
            for (int nh = 0; nh < 2; nh++) {
                uint32_t off = swz(((wn << 5) + (nh << 4) + b_row) * 128 + (ki << 5) + b_kb);
                ldsm4(bhf[nh], kbb + off);
                ldsm4(blf[nh], kbb + 16384 + off);
            }
            #pragma unroll
            for (int mi = 0; mi < 2; mi++)
                #pragma unroll
                for (int ni = 0; ni < 4; ni++) {
                    const uint32_t* bh2 = &bhf[ni >> 1][(ni & 1) << 1];
                    const uint32_t* bl2 = &blf[ni >> 1][(ni & 1) << 1];
                    mma16816(acc[mi][ni], ahf[mi], bh2);
                    mma16816(acc[mi][ni], alf[mi], bh2);
                    mma16816(acc[mi][ni], ahf[mi], bl2);
                }
        }
    };

    // ---------------- pass 1: row sums ----------------
    float rowpart[2][2] = {};
    issue(0, false);
    for (int kt = 0; kt < 16; kt++) {
        if (kt + 1 < 16) { issue(kt + 1, false); CP_WAIT1(); }
        else             { CP_WAIT0(); }
        __syncthreads();
        float acc[2][4][4] = {};
        computeS(kt & 1, acc);
        const float* bw = (const float*)(smx + 17408 + (kt & 1) * 1024);
        const int*   ms = (const int*)(smx + 19456 + (kt & 1) * 512);
        #pragma unroll
        for (int mi = 0; mi < 2; mi++)
            #pragma unroll
            for (int half = 0; half < 2; half++) {
                int r = (wm << 5) + (mi << 4) + g + half * 8;
                float rp = 0.f;
                #pragma unroll
                for (int ni = 0; ni < 4; ni++) {
                    int c = (wn << 5) + (ni << 3) + (tq << 1);
                    float s0 = fmaf(acc[mi][ni][half * 2],     0.125f, bw[c - r + 63]);
                    float s1 = fmaf(acc[mi][ni][half * 2 + 1], 0.125f, bw[c + 1 - r + 63]);
                    rp += (ms[c]     ? __expf(s0) : 0.f);
                    rp += (ms[c + 1] ? __expf(s1) : 0.f);
                }
                rowpart[mi][half] += rp;
            }
        __syncthreads();
    }
    #pragma unroll
    for (int mi = 0; mi < 2; mi++)
        #pragma unroll
        for (int half = 0; half < 2; half++) {
            float v = rowpart[mi][half];
            v += __shfl_xor_sync(0xffffffffu, v, 1);
            v += __shfl_xor_sync(0xffffffffu, v, 2);
            if (tq == 0)
                atomicAdd(&rowsm[(wm << 5) + (mi << 4) + g + half * 8], v);
        }
    __syncthreads();
    if (t < 64) rinv[t] = 1.0f / rowsm[t];
    __syncthreads();
    float riv[2][2];
    #pragma unroll
    for (int mi = 0; mi < 2; mi++)
        #pragma unroll
        for (int half = 0; half < 2; half++)
            riv[mi][half] = rinv[(wm << 5) + (mi << 4) + g + half * 8];

    // ---------------- pass 2: normalized attn store + PV ----------------
    float pv[2][8][4] = {};
    issue(0, true);
    for (int kt = 0; kt < 16; kt++) {
        const int k0 = kt << 7;
        if (kt + 1 < 16) { issue(kt + 1, true); CP_WAIT1(); }
        else             { CP_WAIT0(); }
        __syncthreads();
        float acc[2][4][4] = {};
        computeS(kt & 1, acc);
        const float* bw = (const float*)(smx + 17408 + (kt & 1) * 1024);
        const int*   ms = (const int*)(smx + 19456 + (kt & 1) * 512);
        #pragma unroll
        for (int mi = 0; mi < 2; mi++)
            #pragma unroll
            for (int half = 0; half < 2; half++) {
                int r = (wm << 5) + (mi << 4) + g + half * 8;
                float ri = riv[mi][half];
                #pragma unroll
                for (int ni = 0; ni < 4; ni++) {
                    int c = (wn << 5) + (ni << 3) + (tq << 1);
                    float s0 = fmaf(acc[mi][ni][half * 2],     0.125f, bw[c - r + 63]);
                    float s1 = fmaf(acc[mi][ni][half * 2 + 1], 0.125f, bw[c + 1 - r + 63]);
                    float e0 = (ms[c]     ? __expf(s0) : 0.f) * ri;
                    float e1 = (ms[c + 1] ? __expf(s1) : 0.f) * ri;
                    *(float2*)&attn[((size_t)bh * 2048 + q0 + r) * 2048 + k0 + c] =
                        make_float2(e0, e1);
                    acc[mi][ni][half * 2]     = e0;   // keep normalized P in regs
                    acc[mi][ni][half * 2 + 1] = e1;
                }
            }
        // PV: reuse S accumulator fragments as A operands (m16k16)
        const uint32_t vbase = sb + 20480 + (uint32_t)(kt & 1) * 65536 + 32768;
        #pragma unroll
        for (int j = 0; j < 2; j++) {
            uint32_t bhf[4][4], blf[4][4];
            #pragma unroll
            for (int dvg = 0; dvg < 4; dvg++) {
                uint32_t off = swz(((wn << 5) + (j << 4) + a_row) * 128 + (dvg << 5) + a_kb);
                ldsm4t(bhf[dvg], vbase + off);
                ldsm4t(blf[dvg], vbase + 16384 + off);
            }
            #pragma unroll
            for (int mi = 0; mi < 2; mi++) {
                uint32_t Ah[4], Al[4];
                Ah[0] = pk2(acc[mi][2*j][0],   acc[mi][2*j][1],   Al[0]);
                Ah[1] = pk2(acc[mi][2*j][2],   acc[mi][2*j][3],   Al[1]);
                Ah[2] = pk2(acc[mi][2*j+1][0], acc[mi][2*j+1][1], Al[2]);
                Ah[3] = pk2(acc[mi][2*j+1][2], acc[mi][2*j+1][3], Al[3]);
                #pragma unroll
                for (int dvg = 0; dvg < 4; dvg++)
                    #pragma unroll
                    for (int n8 = 0; n8 < 2; n8++) {
                        float* d = pv[mi][dvg * 2 + n8];
                        mma16816(d, Ah, &bhf[dvg][n8 << 1]);
                        mma16816(d, Al, &bhf[dvg][n8 << 1]);
                        mma16816(d, Ah, &blf[dvg][n8 << 1]);
                    }
            }
        }
        __syncthreads();
    }

    // ---------------- cross-warp PV reduction + ctx store ----------------
    #pragma unroll
    for (int mi = 0; mi < 2; mi++)
        #pragma unroll
        for (int ni = 0; ni < 8; ni++)
            #pragma unroll
            for (int half = 0; half < 2; half++) {
                int row = (wm << 5) + (mi << 4) + g + half * 8;
                uint32_t off = 20480 + (uint32_t)wn * 16384 + row * 256 + ((ni << 3) + (tq << 1)) * 4;
                *(float2*)(smx + off) = make_float2(pv[mi][ni][half * 2], pv[mi][ni][half * 2 + 1]);
            }
    __syncthreads();
    #pragma unroll
    for (int i = 0; i < 8; i++) {
        int idx = t + (i << 8);
        int row = idx >> 5, dvp = idx & 31;
        float sx = 0.f, sy = 0.f;
        #pragma unroll
        for (int w = 0; w < 4; w++) {
            float2 v = *(float2*)(smx + 20480 + w * 16384 + row * 256 + dvp * 8);
            sx += v.x; sy += v.y;
        }
        uint32_t lo, hi = pk2(sx, sy, lo);
        size_t o = ((size_t)(b * 2048 + q0 + row)) * 1024 + (h << 6) + dvp * 2;
        *(uint32_t*)(g_Chi + o) = hi;
        *(uint32_t*)(g_Clo + o) = lo;
    }
}

// ---------------- launch --------------------------------------------------------
#define PROJ_SMEM 131072
#define ATT_SMEM  151552

extern "C" void kernel_launch(void* const* d_in, const int* in_sizes, int n_in,
                              void* d_out, int out_size) {
    const float* hs   = (const float*)d_in[0];
    const int*   mask = (const int*)d_in[1];
    const float* Wq   = (const float*)d_in[2];
    const float* Wk   = (const float*)d_in[3];
    const float* Wv   = (const float*)d_in[4];
    const float* Wo   = (const float*)d_in[5];
    const float* rb   = (const float*)d_in[6];
    float* out  = (float*)d_out;
    float* attn = out + 4194304;

    cudaFuncSetAttribute(proj_gemm,  cudaFuncAttributeMaxDynamicSharedMemorySize, PROJ_SMEM);
    cudaFuncSetAttribute(attn_fused, cudaFuncAttributeMaxDynamicSharedMemorySize, ATT_SMEM);

    bias_init<<<16, 256>>>(rb);
    split_x<<<4096, 256>>>(hs);
    wsplit<<<dim3(32, 32, 4), dim3(32, 8)>>>(Wq, Wk, Wv, Wo);

    proj_gemm<<<dim3(8, 32, 3), 256, PROJ_SMEM>>>(nullptr, 1);   // Q,K,V fused

    attn_fused<<<dim3(32, 32), 256, ATT_SMEM>>>(mask, attn);     // softmax+attn+ctx

    proj_gemm<<<dim3(8, 32, 1), 256, PROJ_SMEM>>>(out, 0);       // ctx @ Wo
}

// round 9
// speedup vs baseline: 2.4797x; 1.0508x over previous
#include <cuda_runtime.h>
#include <cuda_bf16.h>
#include <cstdint>

// ---------------- scratch (static device arrays; no cudaMalloc) -------------
__device__ __align__(16) __nv_bfloat16 g_Xhi[4194304], g_Xlo[4194304];
__device__ __align__(16) __nv_bfloat16 g_Whi[4][1048576], g_Wlo[4][1048576];
__device__ __align__(16) __nv_bfloat16 g_Qhi[4194304], g_Qlo[4194304];
__device__ __align__(16) __nv_bfloat16 g_Khi[4194304], g_Klo[4194304];
__device__ __align__(16) __nv_bfloat16 g_Vhi[4194304], g_Vlo[4194304]; // [bh][s][dkv]
__device__ __align__(16) __nv_bfloat16 g_Chi[4194304], g_Clo[4194304]; // [m][1024]
__device__ float g_bias[16 * 4096];

// ---------------- helpers -----------------------------------------------------
__device__ __forceinline__ uint32_t smem_u32(const void* p) {
    uint32_t a;
    asm("{ .reg .u64 t; cvta.to.shared.u64 t, %1; cvt.u32.u64 %0, t; }" : "=r"(a) : "l"(p));
    return a;
}
__device__ __forceinline__ uint32_t swz(uint32_t off) { return off ^ ((off >> 3) & 0x70); }

__device__ __forceinline__ void cpa16(uint32_t saddr, const void* g) {
    asm volatile("cp.async.cg.shared.global [%0], [%1], 16;" :: "r"(saddr), "l"(g));
}
#define CP_COMMIT() asm volatile("cp.async.commit_group;" ::: "memory")
#define CP_WAIT1()  asm volatile("cp.async.wait_group 1;" ::: "memory")
#define CP_WAIT0()  asm volatile("cp.async.wait_group 0;" ::: "memory")

__device__ __forceinline__ void ldsm4(uint32_t* r, uint32_t addr) {
    asm volatile("ldmatrix.sync.aligned.m8n8.x4.shared.b16 {%0,%1,%2,%3}, [%4];"
        : "=r"(r[0]), "=r"(r[1]), "=r"(r[2]), "=r"(r[3]) : "r"(addr));
}
__device__ __forceinline__ void ldsm4t(uint32_t* r, uint32_t addr) {
    asm volatile("ldmatrix.sync.aligned.m8n8.x4.trans.shared.b16 {%0,%1,%2,%3}, [%4];"
        : "=r"(r[0]), "=r"(r[1]), "=r"(r[2]), "=r"(r[3]) : "r"(addr));
}
__device__ __forceinline__ void mma16816(float* d, const uint32_t* a, const uint32_t* b) {
    asm volatile("mma.sync.aligned.m16n8k16.row.col.f32.bf16.bf16.f32 "
        "{%0,%1,%2,%3}, {%4,%5,%6,%7}, {%8,%9}, {%0,%1,%2,%3};"
        : "+f"(d[0]), "+f"(d[1]), "+f"(d[2]), "+f"(d[3])
        : "r"(a[0]), "r"(a[1]), "r"(a[2]), "r"(a[3]), "r"(b[0]), "r"(b[1]));
}
__device__ __forceinline__ uint32_t pk2(float a, float b, uint32_t& lo) {
    __nv_bfloat162 h, l;
    h.x = __float2bfloat16_rn(a); h.y = __float2bfloat16_rn(b);
    l.x = __float2bfloat16_rn(a - __bfloat162float(h.x));
    l.y = __float2bfloat16_rn(b - __bfloat162float(h.y));
    lo = *(uint32_t*)&l;
    return *(uint32_t*)&h;
}

// ---------------- prep kernels -------------------------------------------------
__global__ void bias_init(const float* __restrict__ rel_bias) {
    int d = blockIdx.x * 256 + threadIdx.x;
    if (d >= 4096) return;
    int n = -(d - 2048);
    int ret = 0;
    if (n < 0) { ret = 16; n = -n; }
    int bucket;
    if      (n <  8) bucket = n;
    else if (n < 12) bucket = 8;
    else if (n < 16) bucket = 9;
    else if (n < 23) bucket = 10;
    else if (n < 32) bucket = 11;
    else if (n < 46) bucket = 12;
    else if (n < 64) bucket = 13;
    else if (n < 91) bucket = 14;
    else             bucket = 15;
    bucket += ret;
    #pragma unroll
    for (int h = 0; h < 16; h++)
        g_bias[h * 4096 + d] = rel_bias[bucket * 16 + h];
}

__global__ void split_x(const float* __restrict__ src) {
    size_t i = ((size_t)blockIdx.x * 256 + threadIdx.x) * 4;
    float4 v = *(const float4*)(src + i);
    float x[4] = {v.x, v.y, v.z, v.w};
    #pragma unroll
    for (int j = 0; j < 4; j++) {
        __nv_bfloat16 hh = __float2bfloat16_rn(x[j]);
        g_Xhi[i + j] = hh;
        g_Xlo[i + j] = __float2bfloat16_rn(x[j] - __bfloat162float(hh));
    }
}

__global__ void wsplit(const float* __restrict__ W0, const float* __restrict__ W1,
                       const float* __restrict__ W2, const float* __restrict__ W3) {
    __shared__ float tile[32][33];
    const float* W = blockIdx.z == 0 ? W0 : blockIdx.z == 1 ? W1 : blockIdx.z == 2 ? W2 : W3;
    int n0 = blockIdx.x * 32, k0 = blockIdx.y * 32;
    int tx = threadIdx.x, ty = threadIdx.y;
    #pragma unroll
    for (int j = 0; j < 4; j++)
        tile[ty + j * 8][tx] = W[(size_t)(k0 + ty + j * 8) * 1024 + n0 + tx];
    __syncthreads();
    #pragma unroll
    for (int j = 0; j < 4; j++) {
        float x = tile[tx][ty + j * 8];
        __nv_bfloat16 hh = __float2bfloat16_rn(x);
        size_t o = (size_t)(n0 + ty + j * 8) * 1024 + k0 + tx;     // [n][k]
        g_Whi[blockIdx.z][o] = hh;
        g_Wlo[blockIdx.z][o] = __float2bfloat16_rn(x - __bfloat162float(hh));
    }
}

// ---------------- unified 128x128 HMMA GEMM, 3-stage cp.async pipeline ---------
__global__ __launch_bounds__(256) void proj_gemm(float* __restrict__ outp, int qkv) {
    extern __shared__ __align__(1024) char smx[];
    const uint32_t sb = smem_u32(smx);
    const int t = threadIdx.x, lane = t & 31, wid = t >> 5;
    const int wm = wid >> 2, wn = wid & 3;
    const int m0 = blockIdx.y << 7, n0 = blockIdx.x << 7;
    const int mode = qkv ? (int)blockIdx.z : 3;
    const __nv_bfloat16* Ah = (mode == 3) ? g_Chi : g_Xhi;
    const __nv_bfloat16* Al = (mode == 3) ? g_Clo : g_Xlo;
    const __nv_bfloat16* Bh = g_Whi[mode];
    const __nv_bfloat16* Bl = g_Wlo[mode];

    auto issue = [&](int kc) {
        const int kb = kc << 6;
        const uint32_t stb = sb + (uint32_t)(kc % 3) * 65536;
        #pragma unroll
        for (int i = 0; i < 4; i++) {
            int idx = t + (i << 8);
            int row = idx >> 3, ge = (idx & 7) << 3;
            uint32_t so = swz(row * 128 + (ge << 1));
            size_t goa = (size_t)(m0 + row) * 1024 + kb + ge;
            size_t gob = (size_t)(n0 + row) * 1024 + kb + ge;
            cpa16(stb + so,         Ah + goa);
            cpa16(stb + 16384 + so, Al + goa);
            cpa16(stb + 32768 + so, Bh + gob);
            cpa16(stb + 49152 + so, Bl + gob);
        }
        CP_COMMIT();
    };

    const uint32_t a_row = (lane & 7) + ((lane >> 3) & 1) * 8;
    const uint32_t a_kb  = (lane >> 4) * 16;
    const uint32_t b_row = (lane & 7) + (lane >> 4) * 8;
    const uint32_t b_kb  = ((lane >> 3) & 1) * 16;

    float acc[4][4][4] = {};
    issue(0); issue(1);
    for (int kc = 0; kc < 16; kc++) {
        if (kc == 15) { CP_WAIT0(); } else { CP_WAIT1(); }
        __syncthreads();
        const uint32_t stb = sb + (uint32_t)(kc % 3) * 65536;
        #pragma unroll
        for (int ki = 0; ki < 4; ki++) {
            uint32_t ahf[4][4], alf[4][4], bhf[2][4], blf[2][4];
            #pragma unroll
            for (int mi = 0; mi < 4; mi++) {
                uint32_t off = swz(((wm << 6) + (mi << 4) + a_row) * 128 + (ki << 5) + a_kb);
                ldsm4(ahf[mi], stb + off);
                ldsm4(alf[mi], stb + 16384 + off);
            }
            #pragma unroll
            for (int nh = 0; nh < 2; nh++) {
                uint32_t off = swz(((wn << 5) + (nh << 4) + b_row) * 128 + (ki << 5) + b_kb);
                ldsm4(bhf[nh], stb + 32768 + off);
                ldsm4(blf[nh], stb + 49152 + off);
            }
            #pragma unroll
            for (int mi = 0; mi < 4; mi++)
                #pragma unroll
                for (int ni = 0; ni < 4; ni++) {
                    const uint32_t* bh2 = &bhf[ni >> 1][(ni & 1) << 1];
                    const uint32_t* bl2 = &blf[ni >> 1][(ni & 1) << 1];
                    mma16816(acc[mi][ni], ahf[mi], bh2);
                    mma16816(acc[mi][ni], alf[mi], bh2);
                    mma16816(acc[mi][ni], ahf[mi], bl2);
                }
        }
        if (kc + 2 < 16) issue(kc + 2);
    }

    const int g = lane >> 2, tq = lane & 3;
    #pragma unroll
    for (int mi = 0; mi < 4; mi++) {
        #pragma unroll
        for (int ni = 0; ni < 4; ni++) {
            #pragma unroll
            for (int half = 0; half < 2; half++) {
                int r = (wm << 6) + (mi << 4) + g + half * 8;
                int c = (wn << 5) + (ni << 3) + (tq << 1);
                float v0 = acc[mi][ni][half * 2], v1 = acc[mi][ni][half * 2 + 1];
                int m = m0 + r, n = n0 + c;
                if (mode == 3) {
                    *(float2*)&outp[(size_t)m * 1024 + n] = make_float2(v0, v1);
                } else {
                    uint32_t lo, hi = pk2(v0, v1, lo);
                    int b = m >> 11, s = m & 2047, hd = n >> 6, dk = n & 63;
                    size_t o = (((size_t)(b * 16 + hd) * 2048) + s) * 64 + dk;
                    __nv_bfloat16* dh = (mode == 0) ? g_Qhi : (mode == 1) ? g_Khi : g_Vhi;
                    __nv_bfloat16* dl = (mode == 0) ? g_Qlo : (mode == 1) ? g_Klo : g_Vlo;
                    *(uint32_t*)(dh + o) = hi;
                    *(uint32_t*)(dl + o) = lo;
                }
            }
        }
    }
}

// ---------------- fused attention: 64q-tile, two-pass softmax + PV -------------
// smem: QH 0 (8K), QL 8192 (8K), rowsm 16384 (64f), rinv 16640 (64f),
//       bias stage s @ 17408+s*1024 (191f), mask s @ 19456+s*512 (128i),
//       K/V stages @ 20480 + s*65536: {KH +0, KL +16K, VH +32K, VL +48K}
//       PV-reduce buffer reuses 20480.. (64KB) after last tile.
__global__ __launch_bounds__(256) void attn_fused(const int* __restrict__ mask,
                                                  float* __restrict__ attn) {
    extern __shared__ __align__(1024) char smx[];
    const uint32_t sb = smem_u32(smx);
    float* rowsm = (float*)(smx + 16384);
    float* rinv  = (float*)(smx + 16640);
    const int t = threadIdx.x, lane = t & 31, wid = t >> 5;
    const int wm = wid >> 2, wn = wid & 3;          // wm 0..1 (q rows), wn 0..3 (k slice)
    const int q0 = blockIdx.x << 6, bh = blockIdx.y, b = bh >> 4, h = bh & 15;
    const int g = lane >> 2, tq = lane & 3;

    // persistent Q tile (64 x 64 dkv), hi/lo
    #pragma unroll
    for (int i = 0; i < 2; i++) {
        int idx = t + (i << 8);
        int row = idx >> 3, ge = (idx & 7) << 3;
        uint32_t so = swz(row * 128 + (ge << 1));
        size_t go = ((size_t)bh * 2048 + q0 + row) * 64 + ge;
        *(uint4*)(smx + so)        = *(const uint4*)(g_Qhi + go);
        *(uint4*)(smx + 8192 + so) = *(const uint4*)(g_Qlo + go);
    }
    if (t < 64) rowsm[t] = 0.f;
    __syncthreads();

    const uint32_t a_row = (lane & 7) + ((lane >> 3) & 1) * 8;
    const uint32_t a_kb  = (lane >> 4) * 16;
    const uint32_t b_row = (lane & 7) + (lane >> 4) * 8;
    const uint32_t b_kb  = ((lane >> 3) & 1) * 16;

    // hoist Q fragments to registers (k-invariant) for pass 1
    uint32_t qh[4][2][4], ql[4][2][4];
    #pragma unroll
    for (int ki = 0; ki < 4; ki++)
        #pragma unroll
        for (int mi = 0; mi < 2; mi++) {
            uint32_t off = swz(((wm << 5) + (mi << 4) + a_row) * 128 + (ki << 5) + a_kb);
            ldsm4(qh[ki][mi], sb + off);
            ldsm4(ql[ki][mi], sb + 8192 + off);
        }

    auto issue = [&](int kt, bool withV) {
        const int k0 = kt << 7, s = kt & 1;
        const uint32_t stb = sb + 20480 + (uint32_t)s * 65536;
        #pragma unroll
        for (int i = 0; i < 4; i++) {
            int idx = t + (i << 8);
            int row = idx >> 3, ge = (idx & 7) << 3;
            uint32_t so = swz(row * 128 + (ge << 1));
            size_t go = ((size_t)bh * 2048 + k0 + row) * 64 + ge;
            cpa16(stb + so,         g_Khi + go);
            cpa16(stb + 16384 + so, g_Klo + go);
            if (withV) {
                cpa16(stb + 32768 + so, g_Vhi + go);
                cpa16(stb + 49152 + so, g_Vlo + go);
            }
        }
        CP_COMMIT();
        float* bw = (float*)(smx + 17408 + s * 1024);
        int*   ms = (int*)(smx + 19456 + s * 512);
        if (t < 191) bw[t] = g_bias[h * 4096 + (k0 - q0 + 1985) + t];
        if (t < 128) ms[t] = mask[b * 2048 + k0 + t];
    };

    // ---------------- pass 1: row sums (reg-resident Q frags) ----------------
    float rowpart[2][2] = {};
    issue(0, false);
    for (int kt = 0; kt < 16; kt++) {
        if (kt + 1 < 16) { issue(kt + 1, false); CP_WAIT1(); }
        else             { CP_WAIT0(); }
        __syncthreads();
        const uint32_t kbb = sb + 20480 + (uint32_t)(kt & 1) * 65536;
        float acc[2][4][4] = {};
        #pragma unroll
        for (int ki = 0; ki < 4; ki++) {
            uint32_t bhf[2][4], blf[2][4];
            #pragma unroll
            for (int nh = 0; nh < 2; nh++) {
                uint32_t off = swz(((wn << 5) + (nh << 4) + b_row) * 128 + (ki << 5) + b_kb);
                ldsm4(bhf[nh], kbb + off);
                ldsm4(blf[nh], kbb + 16384 + off);
            }
            #pragma unroll
            for (int mi = 0; mi < 2; mi++)
                #pragma unroll
                for (int ni = 0; ni < 4; ni++) {
                    const uint32_t* bh2 = &bhf[ni >> 1][(ni & 1) << 1];
                    const uint32_t* bl2 = &blf[ni >> 1][(ni & 1) << 1];
                    mma16816(acc[mi][ni], qh[ki][mi], bh2);
                    mma16816(acc[mi][ni], ql[ki][mi], bh2);
                    mma16816(acc[mi][ni], qh[ki][mi], bl2);
                }
        }
        const float* bw = (const float*)(smx + 17408 + (kt & 1) * 1024);
        const int*   ms = (const int*)(smx + 19456 + (kt & 1) * 512);
        #pragma unroll
        for (int mi = 0; mi < 2; mi++)
            #pragma unroll
            for (int half = 0; half < 2; half++) {
                int r = (wm << 5) + (mi << 4) + g + half * 8;
                float rp = 0.f;
                #pragma unroll
                for (int ni = 0; ni < 4; ni++) {
                    int c = (wn << 5) + (ni << 3) + (tq << 1);
                    float s0 = fmaf(acc[mi][ni][half * 2],     0.125f, bw[c - r + 63]);
                    float s1 = fmaf(acc[mi][ni][half * 2 + 1], 0.125f, bw[c + 1 - r + 63]);
                    rp += (ms[c]     ? __expf(s0) : 0.f);
                    rp += (ms[c + 1] ? __expf(s1) : 0.f);
                }
                rowpart[mi][half] += rp;
            }
        __syncthreads();
    }
    #pragma unroll
    for (int mi = 0; mi < 2; mi++)
        #pragma unroll
        for (int half = 0; half < 2; half++) {
            float v = rowpart[mi][half];
            v += __shfl_xor_sync(0xffffffffu, v, 1);
            v += __shfl_xor_sync(0xffffffffu, v, 2);
            if (tq == 0)
                atomicAdd(&rowsm[(wm << 5) + (mi << 4) + g + half * 8], v);
        }
    __syncthreads();
    if (t < 64) rinv[t] = 1.0f / rowsm[t];
    __syncthreads();
    float riv[2][2];
    #pragma unroll
    for (int mi = 0; mi < 2; mi++)
        #pragma unroll
        for (int half = 0; half < 2; half++)
            riv[mi][half] = rinv[(wm << 5) + (mi << 4) + g + half * 8];

    // ---------------- pass 2: normalized attn store + PV ----------------
    float pv[2][8][4] = {};
    issue(0, true);
    for (int kt = 0; kt < 16; kt++) {
        const int k0 = kt << 7;
        if (kt + 1 < 16) { issue(kt + 1, true); CP_WAIT1(); }
        else             { CP_WAIT0(); }
        __syncthreads();
        const uint32_t kbb = sb + 20480 + (uint32_t)(kt & 1) * 65536;
        float acc[2][4][4] = {};
        #pragma unroll
        for (int ki = 0; ki < 4; ki++) {
            uint32_t bhf[2][4], blf[2][4];
            #pragma unroll
            for (int nh = 0; nh < 2; nh++) {
                uint32_t off = swz(((wn << 5) + (nh << 4) + b_row) * 128 + (ki << 5) + b_kb);
                ldsm4(bhf[nh], kbb + off);
                ldsm4(blf[nh], kbb + 16384 + off);
            }
            #pragma unroll
            for (int mi = 0; mi < 2; mi++)
                #pragma unroll
                for (int ni = 0; ni < 4; ni++) {
                    const uint32_t* bh2 = &bhf[ni >> 1][(ni & 1) << 1];
                    const uint32_t* bl2 = &blf[ni >> 1][(ni & 1) << 1];
                    mma16816(acc[mi][ni], qh[ki][mi], bh2);
                    mma16816(acc[mi][ni], ql[ki][mi], bh2);
                    mma16816(acc[mi][ni], qh[ki][mi], bl2);
                }
        }
        const float* bw = (const float*)(smx + 17408 + (kt & 1) * 1024);
        const int*   ms = (const int*)(smx + 19456 + (kt & 1) * 512);
        #pragma unroll
        for (int mi = 0; mi < 2; mi++)
            #pragma unroll
            for (int half = 0; half < 2; half++) {
                int r = (wm << 5) + (mi << 4) + g + half * 8;
                float ri = riv[mi][half];
                #pragma unroll
                for (int ni = 0; ni < 4; ni++) {
                    int c = (wn << 5) + (ni << 3) + (tq << 1);
                    float s0 = fmaf(acc[mi][ni][half * 2],     0.125f, bw[c - r + 63]);
                    float s1 = fmaf(acc[mi][ni][half * 2 + 1], 0.125f, bw[c + 1 - r + 63]);
                    float e0 = (ms[c]     ? __expf(s0) : 0.f) * ri;
                    float e1 = (ms[c + 1] ? __expf(s1) : 0.f) * ri;
                    *(float2*)&attn[((size_t)bh * 2048 + q0 + r) * 2048 + k0 + c] =
                        make_float2(e0, e1);
                    acc[mi][ni][half * 2]     = e0;   // keep normalized P in regs
                    acc[mi][ni][half * 2 + 1] = e1;
                }
            }
        // PV: reuse S accumulator fragments as A operands (m16k16)
        const uint32_t vbase = sb + 20480 + (uint32_t)(kt & 1) * 65536 + 32768;
        #pragma unroll
        for (int j = 0; j < 2; j++) {
            uint32_t bhf[4][4], blf[4][4];
            #pragma unroll
            for (int dvg = 0; dvg < 4; dvg++) {
                uint32_t off = swz(((wn << 5) + (j << 4) + a_row) * 128 + (dvg << 5) + a_kb);
                ldsm4t(bhf[dvg], vbase + off);
                ldsm4t(blf[dvg], vbase + 16384 + off);
            }
            #pragma unroll
            for (int mi = 0; mi < 2; mi++) {
                uint32_t Ah[4], Al[4];
                Ah[0] = pk2(acc[mi][2*j][0],   acc[mi][2*j][1],   Al[0]);
                Ah[1] = pk2(acc[mi][2*j][2],   acc[mi][2*j][3],   Al[1]);
                Ah[2] = pk2(acc[mi][2*j+1][0], acc[mi][2*j+1][1], Al[2]);
                Ah[3] = pk2(acc[mi][2*j+1][2], acc[mi][2*j+1][3], Al[3]);
                #pragma unroll
                for (int dvg = 0; dvg < 4; dvg++)
                    #pragma unroll
                    for (int n8 = 0; n8 < 2; n8++) {
                        float* d = pv[mi][dvg * 2 + n8];
                        mma16816(d, Ah, &bhf[dvg][n8 << 1]);
                        mma16816(d, Al, &bhf[dvg][n8 << 1]);
                        mma16816(d, Ah, &blf[dvg][n8 << 1]);
                    }
            }
        }
        __syncthreads();
    }

    // ---------------- cross-warp PV reduction + ctx store ----------------
    #pragma unroll
    for (int mi = 0; mi < 2; mi++)
        #pragma unroll
        for (int ni = 0; ni < 8; ni++)
            #pragma unroll
            for (int half = 0; half < 2; half++) {
                int row = (wm << 5) + (mi << 4) + g + half * 8;
                uint32_t off = 20480 + (uint32_t)wn * 16384 + row * 256 + ((ni << 3) + (tq << 1)) * 4;
                *(float2*)(smx + off) = make_float2(pv[mi][ni][half * 2], pv[mi][ni][half * 2 + 1]);
            }
    __syncthreads();
    #pragma unroll
    for (int i = 0; i < 8; i++) {
        int idx = t + (i << 8);
        int row = idx >> 5, dvp = idx & 31;
        float sx = 0.f, sy = 0.f;
        #pragma unroll
        for (int w = 0; w < 4; w++) {
            float2 v = *(float2*)(smx + 20480 + w * 16384 + row * 256 + dvp * 8);
            sx += v.x; sy += v.y;
        }
        uint32_t lo, hi = pk2(sx, sy, lo);
        size_t o = ((size_t)(b * 2048 + q0 + row)) * 1024 + (h << 6) + dvp * 2;
        *(uint32_t*)(g_Chi + o) = hi;
        *(uint32_t*)(g_Clo + o) = lo;
    }
}

// ---------------- launch --------------------------------------------------------
#define PROJ_SMEM 196608
#define ATT_SMEM  151552

extern "C" void kernel_launch(void* const* d_in, const int* in_sizes, int n_in,
                              void* d_out, int out_size) {
    const float* hs   = (const float*)d_in[0];
    const int*   mask = (const int*)d_in[1];
    const float* Wq   = (const float*)d_in[2];
    const float* Wk   = (const float*)d_in[3];
    const float* Wv   = (const float*)d_in[4];
    const float* Wo   = (const float*)d_in[5];
    const float* rb   = (const float*)d_in[6];
    float* out  = (float*)d_out;
    float* attn = out + 4194304;

    cudaFuncSetAttribute(proj_gemm,  cudaFuncAttributeMaxDynamicSharedMemorySize, PROJ_SMEM);
    cudaFuncSetAttribute(attn_fused, cudaFuncAttributeMaxDynamicSharedMemorySize, ATT_SMEM);

    bias_init<<<16, 256>>>(rb);
    split_x<<<4096, 256>>>(hs);
    wsplit<<<dim3(32, 32, 4), dim3(32, 8)>>>(Wq, Wk, Wv, Wo);

    proj_gemm<<<dim3(8, 32, 3), 256, PROJ_SMEM>>>(nullptr, 1);   // Q,K,V fused

    attn_fused<<<dim3(32, 32), 256, ATT_SMEM>>>(mask, attn);     // softmax+attn+ctx

    proj_gemm<<<dim3(8, 32, 1), 256, PROJ_SMEM>>>(out, 0);       // ctx @ Wo
}

// round 10
// speedup vs baseline: 2.5816x; 1.0411x over previous
#include <cuda_runtime.h>
#include <cuda_bf16.h>
#include <cstdint>

// ---------------- scratch (static device arrays; no cudaMalloc) -------------
__device__ __align__(16) __nv_bfloat16 g_Xhi[4194304], g_Xlo[4194304];
__device__ __align__(16) __nv_bfloat16 g_Whi[4][1048576], g_Wlo[4][1048576];
__device__ __align__(16) __nv_bfloat16 g_Qhi[4194304], g_Qlo[4194304];
__device__ __align__(16) __nv_bfloat16 g_Khi[4194304], g_Klo[4194304];
__device__ __align__(16) __nv_bfloat16 g_Vhi[4194304], g_Vlo[4194304]; // [bh][s][dkv]
__device__ __align__(16) __nv_bfloat16 g_Chi[4194304], g_Clo[4194304]; // [m][1024]
__device__ float g_bias[16 * 4096];

// ---------------- helpers -----------------------------------------------------
__device__ __forceinline__ uint32_t smem_u32(const void* p) {
    uint32_t a;
    asm("{ .reg .u64 t; cvta.to.shared.u64 t, %1; cvt.u32.u64 %0, t; }" : "=r"(a) : "l"(p));
    return a;
}
__device__ __forceinline__ uint32_t swz(uint32_t off) { return off ^ ((off >> 3) & 0x70); }

__device__ __forceinline__ void cpa16(uint32_t saddr, const void* g) {
    asm volatile("cp.async.cg.shared.global [%0], [%1], 16;" :: "r"(saddr), "l"(g));
}
#define CP_COMMIT() asm volatile("cp.async.commit_group;" ::: "memory")
#define CP_WAIT1()  asm volatile("cp.async.wait_group 1;" ::: "memory")
#define CP_WAIT0()  asm volatile("cp.async.wait_group 0;" ::: "memory")

__device__ __forceinline__ void ldsm4(uint32_t* r, uint32_t addr) {
    asm volatile("ldmatrix.sync.aligned.m8n8.x4.shared.b16 {%0,%1,%2,%3}, [%4];"
        : "=r"(r[0]), "=r"(r[1]), "=r"(r[2]), "=r"(r[3]) : "r"(addr));
}
__device__ __forceinline__ void ldsm4t(uint32_t* r, uint32_t addr) {
    asm volatile("ldmatrix.sync.aligned.m8n8.x4.trans.shared.b16 {%0,%1,%2,%3}, [%4];"
        : "=r"(r[0]), "=r"(r[1]), "=r"(r[2]), "=r"(r[3]) : "r"(addr));
}
__device__ __forceinline__ void mma16816(float* d, const uint32_t* a, const uint32_t* b) {
    asm volatile("mma.sync.aligned.m16n8k16.row.col.f32.bf16.bf16.f32 "
        "{%0,%1,%2,%3}, {%4,%5,%6,%7}, {%8,%9}, {%0,%1,%2,%3};"
        : "+f"(d[0]), "+f"(d[1]), "+f"(d[2]), "+f"(d[3])
        : "r"(a[0]), "r"(a[1]), "r"(a[2]), "r"(a[3]), "r"(b[0]), "r"(b[1]));
}
__device__ __forceinline__ uint32_t pk2(float a, float b, uint32_t& lo) {
    __nv_bfloat162 h, l;
    h.x = __float2bfloat16_rn(a); h.y = __float2bfloat16_rn(b);
    l.x = __float2bfloat16_rn(a - __bfloat162float(h.x));
    l.y = __float2bfloat16_rn(b - __bfloat162float(h.y));
    lo = *(uint32_t*)&l;
    return *(uint32_t*)&h;
}

// ---------------- prep kernels -------------------------------------------------
__global__ void bias_init(const float* __restrict__ rel_bias) {
    int d = blockIdx.x * 256 + threadIdx.x;
    if (d >= 4096) return;
    int n = -(d - 2048);
    int ret = 0;
    if (n < 0) { ret = 16; n = -n; }
    int bucket;
    if      (n <  8) bucket = n;
    else if (n < 12) bucket = 8;
    else if (n < 16) bucket = 9;
    else if (n < 23) bucket = 10;
    else if (n < 32) bucket = 11;
    else if (n < 46) bucket = 12;
    else if (n < 64) bucket = 13;
    else if (n < 91) bucket = 14;
    else             bucket = 15;
    bucket += ret;
    #pragma unroll
    for (int h = 0; h < 16; h++)
        g_bias[h * 4096 + d] = rel_bias[bucket * 16 + h];
}

__global__ void split_x(const float* __restrict__ src) {
    size_t i = ((size_t)blockIdx.x * 256 + threadIdx.x) * 4;
    float4 v = *(const float4*)(src + i);
    float x[4] = {v.x, v.y, v.z, v.w};
    #pragma unroll
    for (int j = 0; j < 4; j++) {
        __nv_bfloat16 hh = __float2bfloat16_rn(x[j]);
        g_Xhi[i + j] = hh;
        g_Xlo[i + j] = __float2bfloat16_rn(x[j] - __bfloat162float(hh));
    }
}

__global__ void wsplit(const float* __restrict__ W0, const float* __restrict__ W1,
                       const float* __restrict__ W2, const float* __restrict__ W3) {
    __shared__ float tile[32][33];
    const float* W = blockIdx.z == 0 ? W0 : blockIdx.z == 1 ? W1 : blockIdx.z == 2 ? W2 : W3;
    int n0 = blockIdx.x * 32, k0 = blockIdx.y * 32;
    int tx = threadIdx.x, ty = threadIdx.y;
    #pragma unroll
    for (int j = 0; j < 4; j++)
        tile[ty + j * 8][tx] = W[(size_t)(k0 + ty + j * 8) * 1024 + n0 + tx];
    __syncthreads();
    #pragma unroll
    for (int j = 0; j < 4; j++) {
        float x = tile[tx][ty + j * 8];
        __nv_bfloat16 hh = __float2bfloat16_rn(x);
        size_t o = (size_t)(n0 + ty + j * 8) * 1024 + k0 + tx;     // [n][k]
        g_Whi[blockIdx.z][o] = hh;
        g_Wlo[blockIdx.z][o] = __float2bfloat16_rn(x - __bfloat162float(hh));
    }
}

// ---------------- unified 128x128 HMMA GEMM, 3-stage pipeline, 512 thr ---------
__global__ __launch_bounds__(512) void proj_gemm(float* __restrict__ outp, int qkv) {
    extern __shared__ __align__(1024) char smx[];
    const uint32_t sb = smem_u32(smx);
    const int t = threadIdx.x, lane = t & 31, wid = t >> 5;
    const int wm = wid >> 2, wn = wid & 3;         // 4x4 warp grid, 32x32 each
    const int m0 = blockIdx.y << 7, n0 = blockIdx.x << 7;
    const int mode = qkv ? (int)blockIdx.z : 3;
    const __nv_bfloat16* Ah = (mode == 3) ? g_Chi : g_Xhi;
    const __nv_bfloat16* Al = (mode == 3) ? g_Clo : g_Xlo;
    const __nv_bfloat16* Bh = g_Whi[mode];
    const __nv_bfloat16* Bl = g_Wlo[mode];

    auto issue = [&](int kc) {
        const int kb = kc << 6;
        const uint32_t stb = sb + (uint32_t)(kc % 3) * 65536;
        #pragma unroll
        for (int i = 0; i < 2; i++) {
            int idx = t + (i << 9);
            int row = idx >> 3, ge = (idx & 7) << 3;
            uint32_t so = swz(row * 128 + (ge << 1));
            size_t goa = (size_t)(m0 + row) * 1024 + kb + ge;
            size_t gob = (size_t)(n0 + row) * 1024 + kb + ge;
            cpa16(stb + so,         Ah + goa);
            cpa16(stb + 16384 + so, Al + goa);
            cpa16(stb + 32768 + so, Bh + gob);
            cpa16(stb + 49152 + so, Bl + gob);
        }
        CP_COMMIT();
    };

    const uint32_t a_row = (lane & 7) + ((lane >> 3) & 1) * 8;
    const uint32_t a_kb  = (lane >> 4) * 16;
    const uint32_t b_row = (lane & 7) + (lane >> 4) * 8;
    const uint32_t b_kb  = ((lane >> 3) & 1) * 16;

    float acc[2][4][4] = {};
    issue(0); issue(1);
    for (int kc = 0; kc < 16; kc++) {
        if (kc == 15) { CP_WAIT0(); } else { CP_WAIT1(); }
        __syncthreads();
        const uint32_t stb = sb + (uint32_t)(kc % 3) * 65536;
        #pragma unroll
        for (int ki = 0; ki < 4; ki++) {
            uint32_t ahf[2][4], alf[2][4], bhf[2][4], blf[2][4];
            #pragma unroll
            for (int mi = 0; mi < 2; mi++) {
                uint32_t off = swz(((wm << 5) + (mi << 4) + a_row) * 128 + (ki << 5) + a_kb);
                ldsm4(ahf[mi], stb + off);
                ldsm4(alf[mi], stb + 16384 + off);
            }
            #pragma unroll
            for (int nh = 0; nh < 2; nh++) {
                uint32_t off = swz(((wn << 5) + (nh << 4) + b_row) * 128 + (ki << 5) + b_kb);
                ldsm4(bhf[nh], stb + 32768 + off);
                ldsm4(blf[nh], stb + 49152 + off);
            }
            #pragma unroll
            for (int mi = 0; mi < 2; mi++)
                #pragma unroll
                for (int ni = 0; ni < 4; ni++) {
                    const uint32_t* bh2 = &bhf[ni >> 1][(ni & 1) << 1];
                    const uint32_t* bl2 = &blf[ni >> 1][(ni & 1) << 1];
                    mma16816(acc[mi][ni], ahf[mi], bh2);
                    mma16816(acc[mi][ni], alf[mi], bh2);
                    mma16816(acc[mi][ni], ahf[mi], bl2);
                }
        }
        if (kc + 2 < 16) issue(kc + 2);
    }

    const int g = lane >> 2, tq = lane & 3;
    #pragma unroll
    for (int mi = 0; mi < 2; mi++) {
        #pragma unroll
        for (int ni = 0; ni < 4; ni++) {
            #pragma unroll
            for (int half = 0; half < 2; half++) {
                int r = (wm << 5) + (mi << 4) + g + half * 8;
                int c = (wn << 5) + (ni << 3) + (tq << 1);
                float v0 = acc[mi][ni][half * 2], v1 = acc[mi][ni][half * 2 + 1];
                int m = m0 + r, n = n0 + c;
                if (mode == 3) {
                    *(float2*)&outp[(size_t)m * 1024 + n] = make_float2(v0, v1);
                } else {
                    uint32_t lo, hi = pk2(v0, v1, lo);
                    int b = m >> 11, s = m & 2047, hd = n >> 6, dk = n & 63;
                    size_t o = (((size_t)(b * 16 + hd) * 2048) + s) * 64 + dk;
                    __nv_bfloat16* dh = (mode == 0) ? g_Qhi : (mode == 1) ? g_Khi : g_Vhi;
                    __nv_bfloat16* dl = (mode == 0) ? g_Qlo : (mode == 1) ? g_Klo : g_Vlo;
                    *(uint32_t*)(dh + o) = hi;
                    *(uint32_t*)(dl + o) = lo;
                }
            }
        }
    }
}

// ---------------- fused attention: 64q-tile, two-pass softmax + PV, 512 thr ----
// smem: QH 0 (8K), QL 8192, rowsm 16384 (64f), rinv 16640 (64f),
//       bias stage s @ 17408+s*1024 (191f), mask s @ 19456+s*512 (128i),
//       K/V stages @ 20480 + s*65536: {KH +0, KL +16K, VH +32K, VL +48K}
//       PV-reduce buffer reuses 20480.. (64KB) after last tile.
__global__ __launch_bounds__(512) void attn_fused(const int* __restrict__ mask,
                                                  float* __restrict__ attn) {
    extern __shared__ __align__(1024) char smx[];
    const uint32_t sb = smem_u32(smx);
    float* rowsm = (float*)(smx + 16384);
    float* rinv  = (float*)(smx + 16640);
    const int t = threadIdx.x, lane = t & 31, wid = t >> 5;
    const int wm = wid >> 2, wn = wid & 3;          // wm: q 16-row slice, wn: k 32-slice
    const int q0 = blockIdx.x << 6, bh = blockIdx.y, b = bh >> 4, h = bh & 15;
    const int g = lane >> 2, tq = lane & 3;

    // persistent Q tile (64 x 64 dkv), hi/lo — one pass with 512 threads
    {
        int row = t >> 3, ge = (t & 7) << 3;
        uint32_t so = swz(row * 128 + (ge << 1));
        size_t go = ((size_t)bh * 2048 + q0 + row) * 64 + ge;
        *(uint4*)(smx + so)        = *(const uint4*)(g_Qhi + go);
        *(uint4*)(smx + 8192 + so) = *(const uint4*)(g_Qlo + go);
    }
    if (t < 64) rowsm[t] = 0.f;
    __syncthreads();

    const uint32_t a_row = (lane & 7) + ((lane >> 3) & 1) * 8;
    const uint32_t a_kb  = (lane >> 4) * 16;
    const uint32_t b_row = (lane & 7) + (lane >> 4) * 8;
    const uint32_t b_kb  = ((lane >> 3) & 1) * 16;

    auto issue = [&](int kt, bool withV) {
        const int k0 = kt << 7, s = kt & 1;
        const uint32_t stb = sb + 20480 + (uint32_t)s * 65536;
        #pragma unroll
        for (int i = 0; i < 2; i++) {
            int idx = t + (i << 9);
            int row = idx >> 3, ge = (idx & 7) << 3;
            uint32_t so = swz(row * 128 + (ge << 1));
            size_t go = ((size_t)bh * 2048 + k0 + row) * 64 + ge;
            cpa16(stb + so,         g_Khi + go);
            cpa16(stb + 16384 + so, g_Klo + go);
            if (withV) {
                cpa16(stb + 32768 + so, g_Vhi + go);
                cpa16(stb + 49152 + so, g_Vlo + go);
            }
        }
        CP_COMMIT();
        float* bw = (float*)(smx + 17408 + s * 1024);
        int*   ms = (int*)(smx + 19456 + s * 512);
        if (t < 191) bw[t] = g_bias[h * 4096 + (k0 - q0 + 1985) + t];
        if (t < 128) ms[t] = mask[b * 2048 + k0 + t];
    };

    // hoist this warp's Q fragments (16 q-rows, k-invariant), pass-1 scope
    uint32_t qh1[4][4], ql1[4][4];
    #pragma unroll
    for (int ki = 0; ki < 4; ki++) {
        uint32_t off = swz(((wm << 4) + a_row) * 128 + (ki << 5) + a_kb);
        ldsm4(qh1[ki], sb + off);
        ldsm4(ql1[ki], sb + 8192 + off);
    }

    // ---------------- pass 1: row sums ----------------
    float rowpart[2] = {};
    issue(0, false);
    for (int kt = 0; kt < 16; kt++) {
        if (kt + 1 < 16) { issue(kt + 1, false); CP_WAIT1(); }
        else             { CP_WAIT0(); }
        __syncthreads();
        const uint32_t kbb = sb + 20480 + (uint32_t)(kt & 1) * 65536;
        float acc[4][4] = {};
        #pragma unroll
        for (int ki = 0; ki < 4; ki++) {
            uint32_t bhf[2][4], blf[2][4];
            #pragma unroll
            for (int nh = 0; nh < 2; nh++) {
                uint32_t off = swz(((wn << 5) + (nh << 4) + b_row) * 128 + (ki << 5) + b_kb);
                ldsm4(bhf[nh], kbb + off);
                ldsm4(blf[nh], kbb + 16384 + off);
            }
            #pragma unroll
            for (int ni = 0; ni < 4; ni++) {
                const uint32_t* bh2 = &bhf[ni >> 1][(ni & 1) << 1];
                const uint32_t* bl2 = &blf[ni >> 1][(ni & 1) << 1];
                mma16816(acc[ni], qh1[ki], bh2);
                mma16816(acc[ni], ql1[ki], bh2);
                mma16816(acc[ni], qh1[ki], bl2);
            }
        }
        const float* bw = (const float*)(smx + 17408 + (kt & 1) * 1024);
        const int*   ms = (const int*)(smx + 19456 + (kt & 1) * 512);
        #pragma unroll
        for (int half = 0; half < 2; half++) {
            int r = (wm << 4) + g + half * 8;
            float rp = 0.f;
            #pragma unroll
            for (int ni = 0; ni < 4; ni++) {
                int c = (wn << 5) + (ni << 3) + (tq << 1);
                float s0 = fmaf(acc[ni][half * 2],     0.125f, bw[c - r + 63]);
                float s1 = fmaf(acc[ni][half * 2 + 1], 0.125f, bw[c + 1 - r + 63]);
                rp += (ms[c]     ? __expf(s0) : 0.f);
                rp += (ms[c + 1] ? __expf(s1) : 0.f);
            }
            rowpart[half] += rp;
        }
        __syncthreads();
    }
    #pragma unroll
    for (int half = 0; half < 2; half++) {
        float v = rowpart[half];
        v += __shfl_xor_sync(0xffffffffu, v, 1);
        v += __shfl_xor_sync(0xffffffffu, v, 2);
        if (tq == 0)
            atomicAdd(&rowsm[(wm << 4) + g + half * 8], v);
    }
    __syncthreads();
    if (t < 64) rinv[t] = 1.0f / rowsm[t];
    __syncthreads();
    float riv[2];
    #pragma unroll
    for (int half = 0; half < 2; half++)
        riv[half] = rinv[(wm << 4) + g + half * 8];

    // ---------------- pass 2: normalized attn store + PV ----------------
    float pv[8][4] = {};
    issue(0, true);
    for (int kt = 0; kt < 16; kt++) {
        const int k0 = kt << 7;
        if (kt + 1 < 16) { issue(kt + 1, true); CP_WAIT1(); }
        else             { CP_WAIT0(); }
        __syncthreads();
        const uint32_t kbb = sb + 20480 + (uint32_t)(kt & 1) * 65536;
        float acc[4][4] = {};
        #pragma unroll
        for (int ki = 0; ki < 4; ki++) {
            uint32_t bhf[2][4], blf[2][4];
            #pragma unroll
            for (int nh = 0; nh < 2; nh++) {
                uint32_t off = swz(((wn << 5) + (nh << 4) + b_row) * 128 + (ki << 5) + b_kb);
                ldsm4(bhf[nh], kbb + off);
                ldsm4(blf[nh], kbb + 16384 + off);
            }
            #pragma unroll
            for (int ni = 0; ni < 4; ni++) {
                const uint32_t* bh2 = &bhf[ni >> 1][(ni & 1) << 1];
                const uint32_t* bl2 = &blf[ni >> 1][(ni & 1) << 1];
                mma16816(acc[ni], qh1[ki], bh2);
                mma16816(acc[ni], ql1[ki], bh2);
                mma16816(acc[ni], qh1[ki], bl2);
            }
        }
        const float* bw = (const float*)(smx + 17408 + (kt & 1) * 1024);
        const int*   ms = (const int*)(smx + 19456 + (kt & 1) * 512);
        #pragma unroll
        for (int half = 0; half < 2; half++) {
            int r = (wm << 4) + g + half * 8;
            float ri = riv[half];
            #pragma unroll
            for (int ni = 0; ni < 4; ni++) {
                int c = (wn << 5) + (ni << 3) + (tq << 1);
                float s0 = fmaf(acc[ni][half * 2],     0.125f, bw[c - r + 63]);
                float s1 = fmaf(acc[ni][half * 2 + 1], 0.125f, bw[c + 1 - r + 63]);
                float e0 = (ms[c]     ? __expf(s0) : 0.f) * ri;
                float e1 = (ms[c + 1] ? __expf(s1) : 0.f) * ri;
                *(float2*)&attn[((size_t)bh * 2048 + q0 + r) * 2048 + k0 + c] =
                    make_float2(e0, e1);
                acc[ni][half * 2]     = e0;
                acc[ni][half * 2 + 1] = e1;
            }
        }
        // PV: reuse S accumulator fragments as A operands (m16k16)
        const uint32_t vbase = sb + 20480 + (uint32_t)(kt & 1) * 65536 + 32768;
        #pragma unroll
        for (int j = 0; j < 2; j++) {
            uint32_t Ah[4], Al[4];
            Ah[0] = pk2(acc[2*j][0],   acc[2*j][1],   Al[0]);
            Ah[1] = pk2(acc[2*j][2],   acc[2*j][3],   Al[1]);
            Ah[2] = pk2(acc[2*j+1][0], acc[2*j+1][1], Al[2]);
            Ah[3] = pk2(acc[2*j+1][2], acc[2*j+1][3], Al[3]);
            #pragma unroll
            for (int dvg = 0; dvg < 4; dvg++) {
                uint32_t bhf[4], blf[4];
                uint32_t off = swz(((wn << 5) + (j << 4) + a_row) * 128 + (dvg << 5) + a_kb);
                ldsm4t(bhf, vbase + off);
                ldsm4t(blf, vbase + 16384 + off);
                #pragma unroll
                for (int n8 = 0; n8 < 2; n8++) {
                    float* d = pv[dvg * 2 + n8];
                    mma16816(d, Ah, &bhf[n8 << 1]);
                    mma16816(d, Al, &bhf[n8 << 1]);
                    mma16816(d, Ah, &blf[n8 << 1]);
                }
            }
        }
        __syncthreads();
    }

    // ---------------- cross-warp PV reduction + ctx store ----------------
    #pragma unroll
    for (int ni = 0; ni < 8; ni++)
        #pragma unroll
        for (int half = 0; half < 2; half++) {
            int row = (wm << 4) + g + half * 8;
            uint32_t off = 20480 + (uint32_t)wn * 16384 + row * 256 + ((ni << 3) + (tq << 1)) * 4;
            *(float2*)(smx + off) = make_float2(pv[ni][half * 2], pv[ni][half * 2 + 1]);
        }
    __syncthreads();
    #pragma unroll
    for (int i = 0; i < 4; i++) {
        int idx = t + (i << 9);
        int row = idx >> 5, dvp = idx & 31;
        float sx = 0.f, sy = 0.f;
        #pragma unroll
        for (int w = 0; w < 4; w++) {
            float2 v = *(float2*)(smx + 20480 + w * 16384 + row * 256 + dvp * 8);
            sx += v.x; sy += v.y;
        }
        uint32_t lo, hi = pk2(sx, sy, lo);
        size_t o = ((size_t)(b * 2048 + q0 + row)) * 1024 + (h << 6) + dvp * 2;
        *(uint32_t*)(g_Chi + o) = hi;
        *(uint32_t*)(g_Clo + o) = lo;
    }
}

// ---------------- launch --------------------------------------------------------
#define PROJ_SMEM 196608
#define ATT_SMEM  151552

extern "C" void kernel_launch(void* const* d_in, const int* in_sizes, int n_in,
                              void* d_out, int out_size) {
    const float* hs   = (const float*)d_in[0];
    const int*   mask = (const int*)d_in[1];
    const float* Wq   = (const float*)d_in[2];
    const float* Wk   = (const float*)d_in[3];
    const float* Wv   = (const float*)d_in[4];
    const float* Wo   = (const float*)d_in[5];
    const float* rb   = (const float*)d_in[6];
    float* out  = (float*)d_out;
    float* attn = out + 4194304;

    cudaFuncSetAttribute(proj_gemm,  cudaFuncAttributeMaxDynamicSharedMemorySize, PROJ_SMEM);
    cudaFuncSetAttribute(attn_fused, cudaFuncAttributeMaxDynamicSharedMemorySize, ATT_SMEM);

    bias_init<<<16, 256>>>(rb);
    split_x<<<4096, 256>>>(hs);
    wsplit<<<dim3(32, 32, 4), dim3(32, 8)>>>(Wq, Wk, Wv, Wo);

    proj_gemm<<<dim3(8, 32, 3), 512, PROJ_SMEM>>>(nullptr, 1);   // Q,K,V fused

    attn_fused<<<dim3(32, 32), 512, ATT_SMEM>>>(mask, attn);     // softmax+attn+ctx

    proj_gemm<<<dim3(8, 32, 1), 512, PROJ_SMEM>>>(out, 0);       // ctx @ Wo
}